// round 1
// baseline (speedup 1.0000x reference)
#include <cuda_runtime.h>
#include <cuda_bf16.h>

// Problem constants
#define Bq 2
#define Sq 2048
#define DIMq 2048
#define NHq 32
#define NKVq 8
#define HDq 64
#define NTOK (Bq * Sq)          // 4096
#define QDIM (NHq * HDq)        // 2048
#define KVDIM (NKVq * HDq)      // 512

// ---------------------------------------------------------------------------
// Scratch (no allocation allowed -> __device__ globals)
// ---------------------------------------------------------------------------
__device__ float g_Q[NTOK * QDIM];    // 32 MB
__device__ float g_K[NTOK * KVDIM];   // 8 MB
__device__ float g_V[NTOK * KVDIM];   // 8 MB
__device__ float g_O[NTOK * QDIM];    // 32 MB

// ---------------------------------------------------------------------------
// SGEMM: C[M,N] = A[M,K] @ B[K,N], all row-major fp32.
// 128x128 block tile, BK=16, 8x8 per thread, 256 threads.
// M % 128 == 0, N % 128 == 0, K % 16 == 0 (holds for all our shapes).
// ---------------------------------------------------------------------------
__global__ __launch_bounds__(256) void sgemm128(
    const float* __restrict__ A, const float* __restrict__ B,
    float* __restrict__ C, int M, int N, int K)
{
    __shared__ float As[16][128];   // transposed A tile: As[k][m]
    __shared__ float Bs[16][128];   // Bs[k][n]

    const int tid  = threadIdx.x;
    const int brow = blockIdx.y * 128;
    const int bcol = blockIdx.x * 128;

    const int tr = (tid / 16) * 8;  // 0..120 (row of 8x8 tile)
    const int tc = (tid % 16) * 8;  // 0..120 (col of 8x8 tile)

    float acc[8][8];
#pragma unroll
    for (int i = 0; i < 8; i++)
#pragma unroll
        for (int j = 0; j < 8; j++) acc[i][j] = 0.f;

    for (int k0 = 0; k0 < K; k0 += 16) {
        // Load A tile: 128 rows x 16 cols = 512 float4; 2 per thread.
#pragma unroll
        for (int i = 0; i < 2; i++) {
            int r = tid / 4 + i * 64;       // 0..127
            int c = (tid % 4) * 4;          // 0,4,8,12
            float4 v = *(const float4*)&A[(size_t)(brow + r) * K + k0 + c];
            As[c + 0][r] = v.x;
            As[c + 1][r] = v.y;
            As[c + 2][r] = v.z;
            As[c + 3][r] = v.w;
        }
        // Load B tile: 16 rows x 128 cols = 512 float4; 2 per thread.
#pragma unroll
        for (int i = 0; i < 2; i++) {
            int r = tid / 32 + i * 8;       // 0..15
            int c = (tid % 32) * 4;         // 0..124
            *(float4*)&Bs[r][c] = *(const float4*)&B[(size_t)(k0 + r) * N + bcol + c];
        }
        __syncthreads();

#pragma unroll
        for (int kk = 0; kk < 16; kk++) {
            float a[8], b[8];
#pragma unroll
            for (int i = 0; i < 8; i++) a[i] = As[kk][tr + i];
#pragma unroll
            for (int j = 0; j < 8; j++) b[j] = Bs[kk][tc + j];
#pragma unroll
            for (int i = 0; i < 8; i++)
#pragma unroll
                for (int j = 0; j < 8; j++) acc[i][j] += a[i] * b[j];
        }
        __syncthreads();
    }

#pragma unroll
    for (int i = 0; i < 8; i++)
#pragma unroll
        for (int j = 0; j < 8; j += 4) {
            float4 v = make_float4(acc[i][j], acc[i][j + 1], acc[i][j + 2], acc[i][j + 3]);
            *(float4*)&C[(size_t)(brow + tr + i) * N + bcol + tc + j] = v;
        }
}

// ---------------------------------------------------------------------------
// RoPE (in place): T is [NTOK, nheads, 64]; pairs are (2i, 2i+1),
// cos/sin are [Sq, 32] indexed by (seq_pos, pair).
// ---------------------------------------------------------------------------
__global__ void rope_kernel(float* __restrict__ T,
                            const float* __restrict__ cs,
                            const float* __restrict__ sn,
                            int nheads)
{
    int idx = blockIdx.x * blockDim.x + threadIdx.x;
    int total = NTOK * nheads * (HDq / 2);
    if (idx >= total) return;
    int pair  = idx % (HDq / 2);
    int tmp   = idx / (HDq / 2);
    int h     = tmp % nheads;
    int token = tmp / nheads;
    int spos  = token % Sq;

    float c = cs[spos * (HDq / 2) + pair];
    float s = sn[spos * (HDq / 2) + pair];
    float* p = &T[((size_t)token * nheads + h) * HDq + pair * 2];
    float t0 = p[0], t1 = p[1];
    p[0] = t0 * c - t1 * s;
    p[1] = t0 * s + t1 * c;
}

// ---------------------------------------------------------------------------
// Flash attention (fp32, causal, GQA 4:1).
// Grid: (Sq/128, Bq*NHq). 128 threads; thread t owns query row
// sq = blockIdx.x*128 + t. K/V tiles of 64 rows in dynamic smem,
// per-thread score row in smem (stride 65 -> conflict-free).
// ---------------------------------------------------------------------------
__global__ __launch_bounds__(128) void flash_attn(
    const float* __restrict__ Q, const float* __restrict__ K,
    const float* __restrict__ V, float* __restrict__ O)
{
    extern __shared__ float smem[];
    float* Ks = smem;                 // [64][64]
    float* Vs = smem + 64 * HDq;      // [64][64]
    float* Ss = smem + 2 * 64 * HDq;  // [128][65]

    const int bh  = blockIdx.y;
    const int b   = bh / NHq;
    const int h   = bh % NHq;
    const int kvh = h / (NHq / NKVq);
    const int tid = threadIdx.x;
    const int sq  = blockIdx.x * 128 + tid;
    const size_t token = (size_t)b * Sq + sq;

    const float scale = 0.125f;  // 1/sqrt(64)

    float q[HDq], acc[HDq];
#pragma unroll
    for (int d = 0; d < HDq; d++) {
        q[d] = Q[token * QDIM + h * HDq + d] * scale;
        acc[d] = 0.f;
    }
    float m = -1e30f, l = 0.f;

    const int ntiles = blockIdx.x * 2 + 2;  // k tiles of 64 covering [0, sq_max]
    for (int t = 0; t < ntiles; t++) {
        __syncthreads();
        const int base_k = t * 64;
        // Cooperative K/V tile load: 1024 float4 each, 8 per thread.
        for (int i = tid; i < 64 * HDq / 4; i += 128) {
            int row  = i >> 4;
            int col  = (i & 15) << 2;
            size_t kt = ((size_t)b * Sq + base_k + row) * KVDIM + kvh * HDq + col;
            *(float4*)&Ks[row * HDq + col] = *(const float4*)&K[kt];
            *(float4*)&Vs[row * HDq + col] = *(const float4*)&V[kt];
        }
        __syncthreads();

        // Scores
        float tmax = -1e30f;
#pragma unroll 2
        for (int j = 0; j < 64; j++) {
            float s = 0.f;
#pragma unroll
            for (int d = 0; d < HDq; d++) s += q[d] * Ks[j * HDq + d];
            s = (base_k + j <= sq) ? s : -1e30f;
            Ss[tid * 65 + j] = s;
            tmax = fmaxf(tmax, s);
        }

        float newm = fmaxf(m, tmax);
        float corr = __expf(m - newm);
        l *= corr;
#pragma unroll
        for (int d = 0; d < HDq; d++) acc[d] *= corr;

#pragma unroll 2
        for (int j = 0; j < 64; j++) {
            float p = __expf(Ss[tid * 65 + j] - newm);
            l += p;
#pragma unroll
            for (int d = 0; d < HDq; d++) acc[d] += p * Vs[j * HDq + d];
        }
        m = newm;
    }

    float inv = 1.f / l;
#pragma unroll
    for (int d = 0; d < HDq; d++)
        O[token * QDIM + h * HDq + d] = acc[d] * inv;
}

// ---------------------------------------------------------------------------
// Launch
// ---------------------------------------------------------------------------
extern "C" void kernel_launch(void* const* d_in, const int* in_sizes, int n_in,
                              void* d_out, int out_size)
{
    const float* x   = (const float*)d_in[0];  // [2,2048,2048]
    const float* cs  = (const float*)d_in[1];  // [2048,32]
    const float* sn  = (const float*)d_in[2];  // [2048,32]
    const float* Wq  = (const float*)d_in[3];  // [2048,2048]
    const float* Wk  = (const float*)d_in[4];  // [2048,512]
    const float* Wv  = (const float*)d_in[5];  // [2048,512]
    const float* Wo  = (const float*)d_in[6];  // [2048,2048]
    float* out = (float*)d_out;                // [2,2048,2048]

    float *Q, *K, *V, *O;
    cudaGetSymbolAddress((void**)&Q, g_Q);
    cudaGetSymbolAddress((void**)&K, g_K);
    cudaGetSymbolAddress((void**)&V, g_V);
    cudaGetSymbolAddress((void**)&O, g_O);

    // QKV projections
    sgemm128<<<dim3(QDIM / 128, NTOK / 128), 256>>>(x, Wq, Q, NTOK, QDIM, DIMq);
    sgemm128<<<dim3(KVDIM / 128, NTOK / 128), 256>>>(x, Wk, K, NTOK, KVDIM, DIMq);
    sgemm128<<<dim3(KVDIM / 128, NTOK / 128), 256>>>(x, Wv, V, NTOK, KVDIM, DIMq);

    // RoPE on Q and K
    {
        int nq = NTOK * NHq * (HDq / 2);
        rope_kernel<<<(nq + 255) / 256, 256>>>(Q, cs, sn, NHq);
        int nk = NTOK * NKVq * (HDq / 2);
        rope_kernel<<<(nk + 255) / 256, 256>>>(K, cs, sn, NKVq);
    }

    // Flash attention
    {
        int smem_bytes = (2 * 64 * HDq + 128 * 65) * (int)sizeof(float);  // 66048
        cudaFuncSetAttribute(flash_attn, cudaFuncAttributeMaxDynamicSharedMemorySize,
                             smem_bytes);
        flash_attn<<<dim3(Sq / 128, Bq * NHq), 128, smem_bytes>>>(Q, K, V, O);
    }

    // Output projection
    sgemm128<<<dim3(DIMq / 128, NTOK / 128), 256>>>(O, Wo, out, NTOK, DIMq, DIMq);
}

// round 3
// speedup vs baseline: 1.6114x; 1.6114x over previous
#include <cuda_runtime.h>
#include <cuda_bf16.h>
#include <cstdint>

// Problem constants
#define Bq 2
#define Sq 2048
#define DIMq 2048
#define NHq 32
#define NKVq 8
#define HDq 64
#define NTOK (Bq * Sq)          // 4096
#define QDIM (NHq * HDq)        // 2048
#define KVDIM (NKVq * HDq)      // 512

// ---------------------------------------------------------------------------
// Scratch (__device__ globals; no allocation allowed)
// ---------------------------------------------------------------------------
__device__ float g_Q[NTOK * QDIM];    // 32 MB
__device__ float g_K[NTOK * KVDIM];   // 8 MB
__device__ float g_V[NTOK * KVDIM];   // 8 MB
__device__ float g_O[NTOK * QDIM];    // 32 MB

__device__ __forceinline__ uint32_t f2tf32(float f) {
    uint32_t r;
    asm("cvt.rna.tf32.f32 %0, %1;" : "=r"(r) : "f"(f));
    return r;
}

// ---------------------------------------------------------------------------
// tf32 mma.sync GEMM: C[M,N] = A[M,K] @ B[K,N], all row-major fp32.
// CTA tile 128x128, BK=16, 8 warps in 2x4 grid of 64x32 warp tiles.
// mma.m16n8k8.tf32, fp32 accumulate. Double-buffered smem, reg prefetch.
// M%128==0, N%128==0, K%16==0.
// ---------------------------------------------------------------------------
#define SMP 136  // padded row stride (floats): banks 8k+g all distinct

__global__ __launch_bounds__(256, 2) void gemm_mma(
    const float* __restrict__ A, const float* __restrict__ B,
    float* __restrict__ C, int N, int K)
{
    __shared__ float As[2][16][SMP];  // As[buf][k][m]
    __shared__ float Bs[2][16][SMP];  // Bs[buf][k][n]

    const int tid = threadIdx.x;
    const int wid = tid >> 5;
    const int lid = tid & 31;
    const int g   = lid >> 2;   // groupID 0..7
    const int tg  = lid & 3;    // threadID_in_group 0..3

    const int brow = blockIdx.y * 128;
    const int bcol = blockIdx.x * 128;
    const int wm = (wid & 1) * 64;   // warp tile row offset
    const int wn = (wid >> 1) * 32;  // warp tile col offset

    // Global load slots: A tile 128x16 (512 float4), B tile 16x128 (512 float4),
    // 2 float4 each per thread.
    const int sA0 = tid, sA1 = tid + 256;
    const int arow0 = sA0 >> 2, ac0 = (sA0 & 3) * 4;
    const int arow1 = sA1 >> 2, ac1 = (sA1 & 3) * 4;
    const int brow0 = sA0 >> 5, bc0 = (sA0 & 31) * 4;
    const int brow1 = sA1 >> 5, bc1 = (sA1 & 31) * 4;

    const float* Ap0 = A + (size_t)(brow + arow0) * K + ac0;
    const float* Ap1 = A + (size_t)(brow + arow1) * K + ac1;
    const float* Bp0 = B + (size_t)brow0 * N + bcol + bc0;
    const float* Bp1 = B + (size_t)brow1 * N + bcol + bc1;

    float acc[4][4][4];
#pragma unroll
    for (int mi = 0; mi < 4; mi++)
#pragma unroll
        for (int ni = 0; ni < 4; ni++)
#pragma unroll
            for (int q = 0; q < 4; q++) acc[mi][ni][q] = 0.f;

    const int NC = K >> 4;

    // Prologue: tile 0 -> smem buf 0
    {
        float4 va0 = *(const float4*)Ap0;
        float4 va1 = *(const float4*)Ap1;
        float4 vb0 = *(const float4*)Bp0;
        float4 vb1 = *(const float4*)Bp1;
        As[0][ac0 + 0][arow0] = __uint_as_float(f2tf32(va0.x));
        As[0][ac0 + 1][arow0] = __uint_as_float(f2tf32(va0.y));
        As[0][ac0 + 2][arow0] = __uint_as_float(f2tf32(va0.z));
        As[0][ac0 + 3][arow0] = __uint_as_float(f2tf32(va0.w));
        As[0][ac1 + 0][arow1] = __uint_as_float(f2tf32(va1.x));
        As[0][ac1 + 1][arow1] = __uint_as_float(f2tf32(va1.y));
        As[0][ac1 + 2][arow1] = __uint_as_float(f2tf32(va1.z));
        As[0][ac1 + 3][arow1] = __uint_as_float(f2tf32(va1.w));
        Bs[0][brow0][bc0 + 0] = __uint_as_float(f2tf32(vb0.x));
        Bs[0][brow0][bc0 + 1] = __uint_as_float(f2tf32(vb0.y));
        Bs[0][brow0][bc0 + 2] = __uint_as_float(f2tf32(vb0.z));
        Bs[0][brow0][bc0 + 3] = __uint_as_float(f2tf32(vb0.w));
        Bs[0][brow1][bc1 + 0] = __uint_as_float(f2tf32(vb1.x));
        Bs[0][brow1][bc1 + 1] = __uint_as_float(f2tf32(vb1.y));
        Bs[0][brow1][bc1 + 2] = __uint_as_float(f2tf32(vb1.z));
        Bs[0][brow1][bc1 + 3] = __uint_as_float(f2tf32(vb1.w));
    }
    __syncthreads();

    for (int kc = 0; kc < NC; kc++) {
        const int cur = kc & 1;
        const int nxt = cur ^ 1;

        // Prefetch next tile into registers
        float4 va0, va1, vb0, vb1;
        const bool has_next = (kc + 1) < NC;
        if (has_next) {
            const int ko = (kc + 1) << 4;
            va0 = *(const float4*)(Ap0 + ko);
            va1 = *(const float4*)(Ap1 + ko);
            vb0 = *(const float4*)(Bp0 + (size_t)ko * N);
            vb1 = *(const float4*)(Bp1 + (size_t)ko * N);
        }

        // Compute on current buffer: 2 k-slices of 8
#pragma unroll
        for (int ks = 0; ks < 16; ks += 8) {
            uint32_t af[4][4], bf[4][2];
#pragma unroll
            for (int mi = 0; mi < 4; mi++) {
                const int rb = wm + mi * 16;
                af[mi][0] = __float_as_uint(As[cur][ks + tg][rb + g]);
                af[mi][1] = __float_as_uint(As[cur][ks + tg][rb + g + 8]);
                af[mi][2] = __float_as_uint(As[cur][ks + tg + 4][rb + g]);
                af[mi][3] = __float_as_uint(As[cur][ks + tg + 4][rb + g + 8]);
            }
#pragma unroll
            for (int ni = 0; ni < 4; ni++) {
                const int cb = wn + ni * 8;
                bf[ni][0] = __float_as_uint(Bs[cur][ks + tg][cb + g]);
                bf[ni][1] = __float_as_uint(Bs[cur][ks + tg + 4][cb + g]);
            }
#pragma unroll
            for (int mi = 0; mi < 4; mi++)
#pragma unroll
                for (int ni = 0; ni < 4; ni++) {
                    asm volatile(
                        "mma.sync.aligned.m16n8k8.row.col.f32.tf32.tf32.f32 "
                        "{%0,%1,%2,%3}, {%4,%5,%6,%7}, {%8,%9}, {%0,%1,%2,%3};"
                        : "+f"(acc[mi][ni][0]), "+f"(acc[mi][ni][1]),
                          "+f"(acc[mi][ni][2]), "+f"(acc[mi][ni][3])
                        : "r"(af[mi][0]), "r"(af[mi][1]),
                          "r"(af[mi][2]), "r"(af[mi][3]),
                          "r"(bf[ni][0]), "r"(bf[ni][1]));
                }
        }

        if (has_next) {
            __syncthreads();
            As[nxt][ac0 + 0][arow0] = __uint_as_float(f2tf32(va0.x));
            As[nxt][ac0 + 1][arow0] = __uint_as_float(f2tf32(va0.y));
            As[nxt][ac0 + 2][arow0] = __uint_as_float(f2tf32(va0.z));
            As[nxt][ac0 + 3][arow0] = __uint_as_float(f2tf32(va0.w));
            As[nxt][ac1 + 0][arow1] = __uint_as_float(f2tf32(va1.x));
            As[nxt][ac1 + 1][arow1] = __uint_as_float(f2tf32(va1.y));
            As[nxt][ac1 + 2][arow1] = __uint_as_float(f2tf32(va1.z));
            As[nxt][ac1 + 3][arow1] = __uint_as_float(f2tf32(va1.w));
            Bs[nxt][brow0][bc0 + 0] = __uint_as_float(f2tf32(vb0.x));
            Bs[nxt][brow0][bc0 + 1] = __uint_as_float(f2tf32(vb0.y));
            Bs[nxt][brow0][bc0 + 2] = __uint_as_float(f2tf32(vb0.z));
            Bs[nxt][brow0][bc0 + 3] = __uint_as_float(f2tf32(vb0.w));
            Bs[nxt][brow1][bc1 + 0] = __uint_as_float(f2tf32(vb1.x));
            Bs[nxt][brow1][bc1 + 1] = __uint_as_float(f2tf32(vb1.y));
            Bs[nxt][brow1][bc1 + 2] = __uint_as_float(f2tf32(vb1.z));
            Bs[nxt][brow1][bc1 + 3] = __uint_as_float(f2tf32(vb1.w));
            __syncthreads();
        }
    }

    // Epilogue: c0,c1 -> (row, 2tg), (row, 2tg+1); c2,c3 -> row+8
#pragma unroll
    for (int mi = 0; mi < 4; mi++) {
#pragma unroll
        for (int ni = 0; ni < 4; ni++) {
            const int row = brow + wm + mi * 16 + g;
            const int col = bcol + wn + ni * 8 + 2 * tg;
            *(float2*)&C[(size_t)row * N + col] =
                make_float2(acc[mi][ni][0], acc[mi][ni][1]);
            *(float2*)&C[(size_t)(row + 8) * N + col] =
                make_float2(acc[mi][ni][2], acc[mi][ni][3]);
        }
    }
}

// ---------------------------------------------------------------------------
// RoPE (in place)
// ---------------------------------------------------------------------------
__global__ void rope_kernel(float* __restrict__ T,
                            const float* __restrict__ cs,
                            const float* __restrict__ sn,
                            int nheads)
{
    int idx = blockIdx.x * blockDim.x + threadIdx.x;
    int total = NTOK * nheads * (HDq / 2);
    if (idx >= total) return;
    int pair  = idx % (HDq / 2);
    int tmp   = idx / (HDq / 2);
    int h     = tmp % nheads;
    int token = tmp / nheads;
    int spos  = token % Sq;

    float c = cs[spos * (HDq / 2) + pair];
    float s = sn[spos * (HDq / 2) + pair];
    float* p = &T[((size_t)token * nheads + h) * HDq + pair * 2];
    float t0 = p[0], t1 = p[1];
    p[0] = t0 * c - t1 * s;
    p[1] = t0 * s + t1 * c;
}

// ---------------------------------------------------------------------------
// Flash attention (fp32, causal, GQA 4:1) — unchanged from R0.
// ---------------------------------------------------------------------------
__global__ __launch_bounds__(128) void flash_attn(
    const float* __restrict__ Q, const float* __restrict__ K,
    const float* __restrict__ V, float* __restrict__ O)
{
    extern __shared__ float smem[];
    float* Ks = smem;
    float* Vs = smem + 64 * HDq;
    float* Ss = smem + 2 * 64 * HDq;

    const int bh  = blockIdx.y;
    const int b   = bh / NHq;
    const int h   = bh % NHq;
    const int kvh = h / (NHq / NKVq);
    const int tid = threadIdx.x;
    const int sq  = blockIdx.x * 128 + tid;
    const size_t token = (size_t)b * Sq + sq;

    const float scale = 0.125f;

    float q[HDq], acc[HDq];
#pragma unroll
    for (int d = 0; d < HDq; d++) {
        q[d] = Q[token * QDIM + h * HDq + d] * scale;
        acc[d] = 0.f;
    }
    float m = -1e30f, l = 0.f;

    const int ntiles = blockIdx.x * 2 + 2;
    for (int t = 0; t < ntiles; t++) {
        __syncthreads();
        const int base_k = t * 64;
        for (int i = tid; i < 64 * HDq / 4; i += 128) {
            int row = i >> 4;
            int col = (i & 15) << 2;
            size_t kt = ((size_t)b * Sq + base_k + row) * KVDIM + kvh * HDq + col;
            *(float4*)&Ks[row * HDq + col] = *(const float4*)&K[kt];
            *(float4*)&Vs[row * HDq + col] = *(const float4*)&V[kt];
        }
        __syncthreads();

        float tmax = -1e30f;
#pragma unroll 2
        for (int j = 0; j < 64; j++) {
            float s = 0.f;
#pragma unroll
            for (int d = 0; d < HDq; d++) s += q[d] * Ks[j * HDq + d];
            s = (base_k + j <= sq) ? s : -1e30f;
            Ss[tid * 65 + j] = s;
            tmax = fmaxf(tmax, s);
        }

        float newm = fmaxf(m, tmax);
        float corr = __expf(m - newm);
        l *= corr;
#pragma unroll
        for (int d = 0; d < HDq; d++) acc[d] *= corr;

#pragma unroll 2
        for (int j = 0; j < 64; j++) {
            float p = __expf(Ss[tid * 65 + j] - newm);
            l += p;
#pragma unroll
            for (int d = 0; d < HDq; d++) acc[d] += p * Vs[j * HDq + d];
        }
        m = newm;
    }

    float inv = 1.f / l;
#pragma unroll
    for (int d = 0; d < HDq; d++)
        O[token * QDIM + h * HDq + d] = acc[d] * inv;
}

// ---------------------------------------------------------------------------
// Launch
// ---------------------------------------------------------------------------
extern "C" void kernel_launch(void* const* d_in, const int* in_sizes, int n_in,
                              void* d_out, int out_size)
{
    const float* x   = (const float*)d_in[0];
    const float* cs  = (const float*)d_in[1];
    const float* sn  = (const float*)d_in[2];
    const float* Wq  = (const float*)d_in[3];
    const float* Wk  = (const float*)d_in[4];
    const float* Wv  = (const float*)d_in[5];
    const float* Wo  = (const float*)d_in[6];
    float* out = (float*)d_out;

    float *Q, *K, *V, *O;
    cudaGetSymbolAddress((void**)&Q, g_Q);
    cudaGetSymbolAddress((void**)&K, g_K);
    cudaGetSymbolAddress((void**)&V, g_V);
    cudaGetSymbolAddress((void**)&O, g_O);

    // QKV projections (tf32 mma.sync tensor cores)
    gemm_mma<<<dim3(QDIM / 128, NTOK / 128), 256>>>(x, Wq, Q, QDIM, DIMq);
    gemm_mma<<<dim3(KVDIM / 128, NTOK / 128), 256>>>(x, Wk, K, KVDIM, DIMq);
    gemm_mma<<<dim3(KVDIM / 128, NTOK / 128), 256>>>(x, Wv, V, KVDIM, DIMq);

    // RoPE
    {
        int nq = NTOK * NHq * (HDq / 2);
        rope_kernel<<<(nq + 255) / 256, 256>>>(Q, cs, sn, NHq);
        int nk = NTOK * NKVq * (HDq / 2);
        rope_kernel<<<(nk + 255) / 256, 256>>>(K, cs, sn, NKVq);
    }

    // Flash attention (fp32)
    {
        int smem_bytes = (2 * 64 * HDq + 128 * 65) * (int)sizeof(float);
        cudaFuncSetAttribute(flash_attn, cudaFuncAttributeMaxDynamicSharedMemorySize,
                             smem_bytes);
        flash_attn<<<dim3(Sq / 128, Bq * NHq), 128, smem_bytes>>>(Q, K, V, O);
    }

    // Output projection
    gemm_mma<<<dim3(DIMq / 128, NTOK / 128), 256>>>(O, Wo, out, DIMq, QDIM);
}

// round 4
// speedup vs baseline: 3.3778x; 2.0961x over previous
#include <cuda_runtime.h>
#include <cuda_bf16.h>
#include <cstdint>

// Problem constants
#define Bq 2
#define Sq 2048
#define DIMq 2048
#define NHq 32
#define NKVq 8
#define HDq 64
#define NTOK (Bq * Sq)          // 4096
#define QDIM (NHq * HDq)        // 2048
#define KVDIM (NKVq * HDq)      // 512

// ---------------------------------------------------------------------------
// Scratch (__device__ globals; no allocation allowed)
// ---------------------------------------------------------------------------
__device__ float g_Q[NTOK * QDIM];    // 32 MB
__device__ float g_K[NTOK * KVDIM];   // 8 MB
__device__ float g_V[NTOK * KVDIM];   // 8 MB
__device__ float g_O[NTOK * QDIM];    // 32 MB

__device__ __forceinline__ uint32_t f2tf32(float f) {
    uint32_t r;
    asm("cvt.rna.tf32.f32 %0, %1;" : "=r"(r) : "f"(f));
    return r;
}

#define MMA_TF32(c, a0, a1, a2, a3, b0, b1)                                  \
    asm volatile(                                                            \
        "mma.sync.aligned.m16n8k8.row.col.f32.tf32.tf32.f32 "                \
        "{%0,%1,%2,%3}, {%4,%5,%6,%7}, {%8,%9}, {%0,%1,%2,%3};"              \
        : "+f"((c)[0]), "+f"((c)[1]), "+f"((c)[2]), "+f"((c)[3])             \
        : "r"(a0), "r"(a1), "r"(a2), "r"(a3), "r"(b0), "r"(b1))

// ---------------------------------------------------------------------------
// tf32 mma.sync GEMM: C[M,N] = A[M,K] @ B[K,N] (row-major fp32). From R3.
// ---------------------------------------------------------------------------
#define SMP 136

__global__ __launch_bounds__(256, 2) void gemm_mma(
    const float* __restrict__ A, const float* __restrict__ B,
    float* __restrict__ C, int N, int K)
{
    __shared__ float As[2][16][SMP];
    __shared__ float Bs[2][16][SMP];

    const int tid = threadIdx.x;
    const int wid = tid >> 5;
    const int lid = tid & 31;
    const int g   = lid >> 2;
    const int tg  = lid & 3;

    const int brow = blockIdx.y * 128;
    const int bcol = blockIdx.x * 128;
    const int wm = (wid & 1) * 64;
    const int wn = (wid >> 1) * 32;

    const int sA0 = tid, sA1 = tid + 256;
    const int arow0 = sA0 >> 2, ac0 = (sA0 & 3) * 4;
    const int arow1 = sA1 >> 2, ac1 = (sA1 & 3) * 4;
    const int brow0 = sA0 >> 5, bc0 = (sA0 & 31) * 4;
    const int brow1 = sA1 >> 5, bc1 = (sA1 & 31) * 4;

    const float* Ap0 = A + (size_t)(brow + arow0) * K + ac0;
    const float* Ap1 = A + (size_t)(brow + arow1) * K + ac1;
    const float* Bp0 = B + (size_t)brow0 * N + bcol + bc0;
    const float* Bp1 = B + (size_t)brow1 * N + bcol + bc1;

    float acc[4][4][4];
#pragma unroll
    for (int mi = 0; mi < 4; mi++)
#pragma unroll
        for (int ni = 0; ni < 4; ni++)
#pragma unroll
            for (int q = 0; q < 4; q++) acc[mi][ni][q] = 0.f;

    const int NC = K >> 4;

    {
        float4 va0 = *(const float4*)Ap0;
        float4 va1 = *(const float4*)Ap1;
        float4 vb0 = *(const float4*)Bp0;
        float4 vb1 = *(const float4*)Bp1;
        As[0][ac0 + 0][arow0] = __uint_as_float(f2tf32(va0.x));
        As[0][ac0 + 1][arow0] = __uint_as_float(f2tf32(va0.y));
        As[0][ac0 + 2][arow0] = __uint_as_float(f2tf32(va0.z));
        As[0][ac0 + 3][arow0] = __uint_as_float(f2tf32(va0.w));
        As[0][ac1 + 0][arow1] = __uint_as_float(f2tf32(va1.x));
        As[0][ac1 + 1][arow1] = __uint_as_float(f2tf32(va1.y));
        As[0][ac1 + 2][arow1] = __uint_as_float(f2tf32(va1.z));
        As[0][ac1 + 3][arow1] = __uint_as_float(f2tf32(va1.w));
        Bs[0][brow0][bc0 + 0] = __uint_as_float(f2tf32(vb0.x));
        Bs[0][brow0][bc0 + 1] = __uint_as_float(f2tf32(vb0.y));
        Bs[0][brow0][bc0 + 2] = __uint_as_float(f2tf32(vb0.z));
        Bs[0][brow0][bc0 + 3] = __uint_as_float(f2tf32(vb0.w));
        Bs[0][brow1][bc1 + 0] = __uint_as_float(f2tf32(vb1.x));
        Bs[0][brow1][bc1 + 1] = __uint_as_float(f2tf32(vb1.y));
        Bs[0][brow1][bc1 + 2] = __uint_as_float(f2tf32(vb1.z));
        Bs[0][brow1][bc1 + 3] = __uint_as_float(f2tf32(vb1.w));
    }
    __syncthreads();

    for (int kc = 0; kc < NC; kc++) {
        const int cur = kc & 1;
        const int nxt = cur ^ 1;

        float4 va0, va1, vb0, vb1;
        const bool has_next = (kc + 1) < NC;
        if (has_next) {
            const int ko = (kc + 1) << 4;
            va0 = *(const float4*)(Ap0 + ko);
            va1 = *(const float4*)(Ap1 + ko);
            vb0 = *(const float4*)(Bp0 + (size_t)ko * N);
            vb1 = *(const float4*)(Bp1 + (size_t)ko * N);
        }

#pragma unroll
        for (int ks = 0; ks < 16; ks += 8) {
            uint32_t af[4][4], bf[4][2];
#pragma unroll
            for (int mi = 0; mi < 4; mi++) {
                const int rb = wm + mi * 16;
                af[mi][0] = __float_as_uint(As[cur][ks + tg][rb + g]);
                af[mi][1] = __float_as_uint(As[cur][ks + tg][rb + g + 8]);
                af[mi][2] = __float_as_uint(As[cur][ks + tg + 4][rb + g]);
                af[mi][3] = __float_as_uint(As[cur][ks + tg + 4][rb + g + 8]);
            }
#pragma unroll
            for (int ni = 0; ni < 4; ni++) {
                const int cb = wn + ni * 8;
                bf[ni][0] = __float_as_uint(Bs[cur][ks + tg][cb + g]);
                bf[ni][1] = __float_as_uint(Bs[cur][ks + tg + 4][cb + g]);
            }
#pragma unroll
            for (int mi = 0; mi < 4; mi++)
#pragma unroll
                for (int ni = 0; ni < 4; ni++)
                    MMA_TF32(acc[mi][ni], af[mi][0], af[mi][1], af[mi][2], af[mi][3],
                             bf[ni][0], bf[ni][1]);
        }

        if (has_next) {
            __syncthreads();
            As[nxt][ac0 + 0][arow0] = __uint_as_float(f2tf32(va0.x));
            As[nxt][ac0 + 1][arow0] = __uint_as_float(f2tf32(va0.y));
            As[nxt][ac0 + 2][arow0] = __uint_as_float(f2tf32(va0.z));
            As[nxt][ac0 + 3][arow0] = __uint_as_float(f2tf32(va0.w));
            As[nxt][ac1 + 0][arow1] = __uint_as_float(f2tf32(va1.x));
            As[nxt][ac1 + 1][arow1] = __uint_as_float(f2tf32(va1.y));
            As[nxt][ac1 + 2][arow1] = __uint_as_float(f2tf32(va1.z));
            As[nxt][ac1 + 3][arow1] = __uint_as_float(f2tf32(va1.w));
            Bs[nxt][brow0][bc0 + 0] = __uint_as_float(f2tf32(vb0.x));
            Bs[nxt][brow0][bc0 + 1] = __uint_as_float(f2tf32(vb0.y));
            Bs[nxt][brow0][bc0 + 2] = __uint_as_float(f2tf32(vb0.z));
            Bs[nxt][brow0][bc0 + 3] = __uint_as_float(f2tf32(vb0.w));
            Bs[nxt][brow1][bc1 + 0] = __uint_as_float(f2tf32(vb1.x));
            Bs[nxt][brow1][bc1 + 1] = __uint_as_float(f2tf32(vb1.y));
            Bs[nxt][brow1][bc1 + 2] = __uint_as_float(f2tf32(vb1.z));
            Bs[nxt][brow1][bc1 + 3] = __uint_as_float(f2tf32(vb1.w));
            __syncthreads();
        }
    }

#pragma unroll
    for (int mi = 0; mi < 4; mi++) {
#pragma unroll
        for (int ni = 0; ni < 4; ni++) {
            const int row = brow + wm + mi * 16 + g;
            const int col = bcol + wn + ni * 8 + 2 * tg;
            *(float2*)&C[(size_t)row * N + col] =
                make_float2(acc[mi][ni][0], acc[mi][ni][1]);
            *(float2*)&C[(size_t)(row + 8) * N + col] =
                make_float2(acc[mi][ni][2], acc[mi][ni][3]);
        }
    }
}

// ---------------------------------------------------------------------------
// RoPE (in place)
// ---------------------------------------------------------------------------
__global__ void rope_kernel(float* __restrict__ T,
                            const float* __restrict__ cs,
                            const float* __restrict__ sn,
                            int nheads)
{
    int idx = blockIdx.x * blockDim.x + threadIdx.x;
    int total = NTOK * nheads * (HDq / 2);
    if (idx >= total) return;
    int pair  = idx % (HDq / 2);
    int tmp   = idx / (HDq / 2);
    int h     = tmp % nheads;
    int token = tmp / nheads;
    int spos  = token % Sq;

    float c = cs[spos * (HDq / 2) + pair];
    float s = sn[spos * (HDq / 2) + pair];
    float* p = &T[((size_t)token * nheads + h) * HDq + pair * 2];
    float t0 = p[0], t1 = p[1];
    p[0] = t0 * c - t1 * s;
    p[1] = t0 * s + t1 * c;
}

// ---------------------------------------------------------------------------
// Tensor-core flash attention (tf32 mma.sync, causal, GQA 4:1).
// CTA: 128 q rows of one (b,h); 8 warps, each an m16 slab. KV tiles of 64.
// QK: Q-frags (regs) x K (smem, stride 68). Softmax on fragments.
// PV: score C-frags reused as A-frags against permuted-row V (stride 72):
//     within each 8-row group, V row r stored at pi(r)= (r>>1) + ((r&1)<<2).
// ---------------------------------------------------------------------------
#define KS_STRIDE 68
#define VS_STRIDE 72
#define FA_SMEM (64 * KS_STRIDE + 64 * VS_STRIDE)  // 8960 floats (Qs overlays)

__global__ __launch_bounds__(256) void flash_mma(
    const float* __restrict__ Q, const float* __restrict__ K,
    const float* __restrict__ V, float* __restrict__ O)
{
    __shared__ float smem[FA_SMEM];
    float* Ks = smem;                    // [64][68]
    float* Vs = smem + 64 * KS_STRIDE;   // [64][72]
    float* Qs = smem;                    // [128][68] (overlays, used first)

    const int bh  = blockIdx.y;
    const int b   = bh >> 5;
    const int h   = bh & 31;
    const int kvh = h >> 2;
    const int qb  = gridDim.x - 1 - blockIdx.x;  // heavy CTAs first
    const int q0  = qb * 128;

    const int tid = threadIdx.x;
    const int wid = tid >> 5;
    const int lid = tid & 31;
    const int g   = lid >> 2;
    const int tg  = lid & 3;
    const int wq  = wid * 16;            // warp's row offset within block

    // ---- Load Q tile (scaled, tf32) into Qs, build fragments ----
#pragma unroll
    for (int j = 0; j < 8; j++) {
        int i = tid + 256 * j;
        int row = i >> 4;
        int c = (i & 15) << 2;
        float4 v = *(const float4*)&Q[((size_t)(b * Sq + q0 + row)) * QDIM + h * HDq + c];
        float4 w;
        w.x = __uint_as_float(f2tf32(v.x * 0.125f));
        w.y = __uint_as_float(f2tf32(v.y * 0.125f));
        w.z = __uint_as_float(f2tf32(v.z * 0.125f));
        w.w = __uint_as_float(f2tf32(v.w * 0.125f));
        *(float4*)&Qs[row * KS_STRIDE + c] = w;
    }
    __syncthreads();

    uint32_t qf[8][4];
#pragma unroll
    for (int kc = 0; kc < 8; kc++) {
        qf[kc][0] = __float_as_uint(Qs[(wq + g) * KS_STRIDE + 8 * kc + tg]);
        qf[kc][1] = __float_as_uint(Qs[(wq + g + 8) * KS_STRIDE + 8 * kc + tg]);
        qf[kc][2] = __float_as_uint(Qs[(wq + g) * KS_STRIDE + 8 * kc + tg + 4]);
        qf[kc][3] = __float_as_uint(Qs[(wq + g + 8) * KS_STRIDE + 8 * kc + tg + 4]);
    }

    float oacc[8][4];
#pragma unroll
    for (int nj = 0; nj < 8; nj++)
#pragma unroll
        for (int q = 0; q < 4; q++) oacc[nj][q] = 0.f;
    float m0 = -1e30f, m1 = -1e30f, l0 = 0.f, l1 = 0.f;

    const int ntiles = 2 * qb + 2;
    const int row0 = q0 + wq + g;        // this thread's two rows
    const int row1 = row0 + 8;

    for (int t = 0; t < ntiles; t++) {
        const int tb = t * 64;
        __syncthreads();  // previous tile's reads complete

        // ---- Load K (as-is) and V (row-permuted) tiles, tf32 ----
#pragma unroll
        for (int j = 0; j < 4; j++) {
            int i = tid + 256 * j;
            int row = i >> 4;
            int c = (i & 15) << 2;
            size_t src = ((size_t)(b * Sq + tb + row)) * KVDIM + kvh * HDq + c;
            float4 kv = *(const float4*)&K[src];
            float4 kw;
            kw.x = __uint_as_float(f2tf32(kv.x));
            kw.y = __uint_as_float(f2tf32(kv.y));
            kw.z = __uint_as_float(f2tf32(kv.z));
            kw.w = __uint_as_float(f2tf32(kv.w));
            *(float4*)&Ks[row * KS_STRIDE + c] = kw;

            float4 vv = *(const float4*)&V[src];
            float4 vw;
            vw.x = __uint_as_float(f2tf32(vv.x));
            vw.y = __uint_as_float(f2tf32(vv.y));
            vw.z = __uint_as_float(f2tf32(vv.z));
            vw.w = __uint_as_float(f2tf32(vv.w));
            int r7 = row & 7;
            int prow = (row & ~7) | ((r7 >> 1) + ((r7 & 1) << 2));
            *(float4*)&Vs[prow * VS_STRIDE + c] = vw;
        }
        __syncthreads();

        // ---- S = Q @ K^T ----
        float sacc[8][4];
#pragma unroll
        for (int ni = 0; ni < 8; ni++)
#pragma unroll
            for (int q = 0; q < 4; q++) sacc[ni][q] = 0.f;

#pragma unroll
        for (int kc = 0; kc < 8; kc++) {
#pragma unroll
            for (int ni = 0; ni < 8; ni++) {
                uint32_t b0 = __float_as_uint(Ks[(8 * ni + g) * KS_STRIDE + 8 * kc + tg]);
                uint32_t b1 = __float_as_uint(Ks[(8 * ni + g) * KS_STRIDE + 8 * kc + tg + 4]);
                MMA_TF32(sacc[ni], qf[kc][0], qf[kc][1], qf[kc][2], qf[kc][3], b0, b1);
            }
        }

        // ---- Causal mask (only near diagonal for this warp) ----
        if (tb + 63 > q0 + wq) {
#pragma unroll
            for (int ni = 0; ni < 8; ni++) {
                int key = tb + 8 * ni + 2 * tg;
                if (key > row0)     sacc[ni][0] = -1e30f;
                if (key + 1 > row0) sacc[ni][1] = -1e30f;
                if (key > row1)     sacc[ni][2] = -1e30f;
                if (key + 1 > row1) sacc[ni][3] = -1e30f;
            }
        }

        // ---- Online softmax ----
        float tmax0 = -1e30f, tmax1 = -1e30f;
#pragma unroll
        for (int ni = 0; ni < 8; ni++) {
            tmax0 = fmaxf(tmax0, fmaxf(sacc[ni][0], sacc[ni][1]));
            tmax1 = fmaxf(tmax1, fmaxf(sacc[ni][2], sacc[ni][3]));
        }
        tmax0 = fmaxf(tmax0, __shfl_xor_sync(0xffffffff, tmax0, 1));
        tmax0 = fmaxf(tmax0, __shfl_xor_sync(0xffffffff, tmax0, 2));
        tmax1 = fmaxf(tmax1, __shfl_xor_sync(0xffffffff, tmax1, 1));
        tmax1 = fmaxf(tmax1, __shfl_xor_sync(0xffffffff, tmax1, 2));

        float nm0 = fmaxf(m0, tmax0);
        float nm1 = fmaxf(m1, tmax1);
        float corr0 = __expf(m0 - nm0);
        float corr1 = __expf(m1 - nm1);

        uint32_t ps[8][4];  // P fragments in A-order: {c0, c2, c1, c3}
        float rs0 = 0.f, rs1 = 0.f;
#pragma unroll
        for (int ni = 0; ni < 8; ni++) {
            float p00 = __expf(sacc[ni][0] - nm0);
            float p01 = __expf(sacc[ni][1] - nm0);
            float p10 = __expf(sacc[ni][2] - nm1);
            float p11 = __expf(sacc[ni][3] - nm1);
            rs0 += p00 + p01;
            rs1 += p10 + p11;
            ps[ni][0] = f2tf32(p00);
            ps[ni][1] = f2tf32(p10);
            ps[ni][2] = f2tf32(p01);
            ps[ni][3] = f2tf32(p11);
        }
        rs0 += __shfl_xor_sync(0xffffffff, rs0, 1);
        rs0 += __shfl_xor_sync(0xffffffff, rs0, 2);
        rs1 += __shfl_xor_sync(0xffffffff, rs1, 1);
        rs1 += __shfl_xor_sync(0xffffffff, rs1, 2);

        l0 = l0 * corr0 + rs0;
        l1 = l1 * corr1 + rs1;
#pragma unroll
        for (int nj = 0; nj < 8; nj++) {
            oacc[nj][0] *= corr0;
            oacc[nj][1] *= corr0;
            oacc[nj][2] *= corr1;
            oacc[nj][3] *= corr1;
        }
        m0 = nm0;
        m1 = nm1;

        // ---- O += P @ V' ----
#pragma unroll
        for (int kc = 0; kc < 8; kc++) {
#pragma unroll
            for (int nj = 0; nj < 8; nj++) {
                uint32_t b0 = __float_as_uint(Vs[(8 * kc + tg) * VS_STRIDE + 8 * nj + g]);
                uint32_t b1 = __float_as_uint(Vs[(8 * kc + tg + 4) * VS_STRIDE + 8 * nj + g]);
                MMA_TF32(oacc[nj], ps[kc][0], ps[kc][1], ps[kc][2], ps[kc][3], b0, b1);
            }
        }
    }

    // ---- Normalize and write ----
    float inv0 = 1.f / l0;
    float inv1 = 1.f / l1;
    const size_t tok0 = (size_t)b * Sq + row0;
#pragma unroll
    for (int nj = 0; nj < 8; nj++) {
        const int col = h * HDq + 8 * nj + 2 * tg;
        *(float2*)&O[tok0 * QDIM + col] =
            make_float2(oacc[nj][0] * inv0, oacc[nj][1] * inv0);
        *(float2*)&O[(tok0 + 8) * QDIM + col] =
            make_float2(oacc[nj][2] * inv1, oacc[nj][3] * inv1);
    }
}

// ---------------------------------------------------------------------------
// Launch
// ---------------------------------------------------------------------------
extern "C" void kernel_launch(void* const* d_in, const int* in_sizes, int n_in,
                              void* d_out, int out_size)
{
    const float* x   = (const float*)d_in[0];
    const float* cs  = (const float*)d_in[1];
    const float* sn  = (const float*)d_in[2];
    const float* Wq  = (const float*)d_in[3];
    const float* Wk  = (const float*)d_in[4];
    const float* Wv  = (const float*)d_in[5];
    const float* Wo  = (const float*)d_in[6];
    float* out = (float*)d_out;

    float *Q, *K, *V, *O;
    cudaGetSymbolAddress((void**)&Q, g_Q);
    cudaGetSymbolAddress((void**)&K, g_K);
    cudaGetSymbolAddress((void**)&V, g_V);
    cudaGetSymbolAddress((void**)&O, g_O);

    // QKV projections (tf32 mma.sync)
    gemm_mma<<<dim3(QDIM / 128, NTOK / 128), 256>>>(x, Wq, Q, QDIM, DIMq);
    gemm_mma<<<dim3(KVDIM / 128, NTOK / 128), 256>>>(x, Wk, K, KVDIM, DIMq);
    gemm_mma<<<dim3(KVDIM / 128, NTOK / 128), 256>>>(x, Wv, V, KVDIM, DIMq);

    // RoPE
    {
        int nq = NTOK * NHq * (HDq / 2);
        rope_kernel<<<(nq + 255) / 256, 256>>>(Q, cs, sn, NHq);
        int nk = NTOK * NKVq * (HDq / 2);
        rope_kernel<<<(nk + 255) / 256, 256>>>(K, cs, sn, NKVq);
    }

    // Tensor-core flash attention
    flash_mma<<<dim3(Sq / 128, Bq * NHq), 256>>>(Q, K, V, O);

    // Output projection
    gemm_mma<<<dim3(DIMq / 128, NTOK / 128), 256>>>(O, Wo, out, DIMq, QDIM);
}

// round 6
// speedup vs baseline: 4.4315x; 1.3119x over previous
#include <cuda_runtime.h>
#include <cuda_fp16.h>
#include <cstdint>

// Problem constants
#define Bq 2
#define Sq 2048
#define DIMq 2048
#define NHq 32
#define NKVq 8
#define HDq 64
#define NTOK (Bq * Sq)          // 4096
#define QDIM (NHq * HDq)        // 2048
#define KVDIM (NKVq * HDq)      // 512

// ---------------------------------------------------------------------------
// Scratch (__device__ globals; no allocation allowed)
// ---------------------------------------------------------------------------
__device__ float  g_Q[NTOK * QDIM];    // 32 MB (fp32: RoPE precision)
__device__ float  g_K[NTOK * KVDIM];   // 8 MB
__device__ float  g_V[NTOK * KVDIM];   // 8 MB
__device__ __half g_O[NTOK * QDIM];    // 16 MB (fp16: quantized by Wo anyway)

__device__ __forceinline__ uint32_t s2u(const void* p) {
    return (uint32_t)__cvta_generic_to_shared(p);
}
__device__ __forceinline__ uint32_t f2h2u(float x, float y) {
    __half2 h = __floats2half2_rn(x, y);
    return *(uint32_t*)&h;
}

#define LDSM4(r0, r1, r2, r3, addr)                                          \
    asm volatile("ldmatrix.sync.aligned.m8n8.x4.shared.b16 {%0,%1,%2,%3}, [%4];" \
                 : "=r"(r0), "=r"(r1), "=r"(r2), "=r"(r3) : "r"(addr))
#define LDSM4T(r0, r1, r2, r3, addr)                                         \
    asm volatile("ldmatrix.sync.aligned.m8n8.x4.trans.shared.b16 {%0,%1,%2,%3}, [%4];" \
                 : "=r"(r0), "=r"(r1), "=r"(r2), "=r"(r3) : "r"(addr))
#define MMA_F16(c, a0, a1, a2, a3, b0, b1)                                   \
    asm volatile(                                                            \
        "mma.sync.aligned.m16n8k16.row.col.f32.f16.f16.f32 "                 \
        "{%0,%1,%2,%3}, {%4,%5,%6,%7}, {%8,%9}, {%0,%1,%2,%3};"              \
        : "+f"((c)[0]), "+f"((c)[1]), "+f"((c)[2]), "+f"((c)[3])             \
        : "r"(a0), "r"(a1), "r"(a2), "r"(a3), "r"(b0), "r"(b1))

// 8 contiguous source elems -> uint4 of 8 halves
template <typename TA>
__device__ __forceinline__ uint4 load8(const TA* p);
template <>
__device__ __forceinline__ uint4 load8<float>(const float* p) {
    float4 a = *(const float4*)p;
    float4 b = *(const float4*)(p + 4);
    uint4 u;
    u.x = f2h2u(a.x, a.y);
    u.y = f2h2u(a.z, a.w);
    u.z = f2h2u(b.x, b.y);
    u.w = f2h2u(b.z, b.w);
    return u;
}
template <>
__device__ __forceinline__ uint4 load8<__half>(const __half* p) {
    return *(const uint4*)p;
}

// ---------------------------------------------------------------------------
// fp16 mma.sync GEMM: C[M,N] = A[M,K] @ B[K,N]; A fp32 or fp16, B fp32.
// CTA 128x128, BK=16, 8 warps (2x4) of 64x32 tiles, m16n8k16, f32 accum.
// ---------------------------------------------------------------------------
template <typename TA>
__global__ __launch_bounds__(256, 2) void gemm_h(
    const TA* __restrict__ A, const float* __restrict__ B,
    float* __restrict__ C, int N, int K)
{
    __shared__ __half As[2][128][24];   // [m][k], pad 16->24 (48B rows)
    __shared__ __half Bs[2][16][136];   // [k][n], pad 128->136 (272B rows)

    const int tid = threadIdx.x;
    const int wid = tid >> 5;
    const int lid = tid & 31;
    const int g   = lid >> 2;
    const int tg  = lid & 3;

    const int brow = blockIdx.y * 128;
    const int bcol = blockIdx.x * 128;
    const int wm = (wid & 1) * 64;
    const int wn = (wid >> 1) * 32;

    // Loaders: A row per 2 threads (8 halves each); B row per 16 threads.
    const int ar = tid >> 1, ac = (tid & 1) * 8;
    const int brr = tid >> 4, bcc = (tid & 15) * 8;
    const TA* Ap = A + (size_t)(brow + ar) * K + ac;
    const float* Bp = B + (size_t)brr * N + bcol + bcc;

    // ldmatrix lane geometry
    const int a_r = wm + (lid & 15);
    const int a_c = 8 * (lid >> 4);
    const int b_k = (lid & 7) + 8 * ((lid >> 3) & 1);
    const int b_n = 8 * (lid >> 4);

    float acc[4][4][4];
#pragma unroll
    for (int mi = 0; mi < 4; mi++)
#pragma unroll
        for (int ni = 0; ni < 4; ni++)
#pragma unroll
            for (int q = 0; q < 4; q++) acc[mi][ni][q] = 0.f;

    const int NC = K >> 4;

    // Prologue: chunk 0 -> buf 0
    *(uint4*)&As[0][ar][ac] = load8<TA>(Ap);
    *(uint4*)&Bs[0][brr][bcc] = load8<float>(Bp);
    __syncthreads();

    for (int kc = 0; kc < NC; kc++) {
        const int cur = kc & 1;
        const int nxt = cur ^ 1;

        uint4 pa, pb;
        const bool has_next = (kc + 1) < NC;
        if (has_next) {
            pa = load8<TA>(Ap + ((kc + 1) << 4));
            pb = load8<float>(Bp + (size_t)((kc + 1) << 4) * N);
        }

        uint32_t af[4][4];
#pragma unroll
        for (int mi = 0; mi < 4; mi++)
            LDSM4(af[mi][0], af[mi][1], af[mi][2], af[mi][3],
                  s2u(&As[cur][a_r + mi * 16][a_c]));

        uint32_t bf[4][2];
#pragma unroll
        for (int nq = 0; nq < 2; nq++)
            LDSM4T(bf[2 * nq][0], bf[2 * nq][1], bf[2 * nq + 1][0], bf[2 * nq + 1][1],
                   s2u(&Bs[cur][b_k][wn + nq * 16 + b_n]));

#pragma unroll
        for (int mi = 0; mi < 4; mi++)
#pragma unroll
            for (int ni = 0; ni < 4; ni++)
                MMA_F16(acc[mi][ni], af[mi][0], af[mi][1], af[mi][2], af[mi][3],
                        bf[ni][0], bf[ni][1]);

        if (has_next) {
            __syncthreads();
            *(uint4*)&As[nxt][ar][ac] = pa;
            *(uint4*)&Bs[nxt][brr][bcc] = pb;
            __syncthreads();
        }
    }

#pragma unroll
    for (int mi = 0; mi < 4; mi++) {
#pragma unroll
        for (int ni = 0; ni < 4; ni++) {
            const int row = brow + wm + mi * 16 + g;
            const int col = bcol + wn + ni * 8 + 2 * tg;
            *(float2*)&C[(size_t)row * N + col] =
                make_float2(acc[mi][ni][0], acc[mi][ni][1]);
            *(float2*)&C[(size_t)(row + 8) * N + col] =
                make_float2(acc[mi][ni][2], acc[mi][ni][3]);
        }
    }
}

// ---------------------------------------------------------------------------
// RoPE (in place, fp32)
// ---------------------------------------------------------------------------
__global__ void rope_kernel(float* __restrict__ T,
                            const float* __restrict__ cs,
                            const float* __restrict__ sn,
                            int nheads)
{
    int idx = blockIdx.x * blockDim.x + threadIdx.x;
    int total = NTOK * nheads * (HDq / 2);
    if (idx >= total) return;
    int pair  = idx % (HDq / 2);
    int tmp   = idx / (HDq / 2);
    int h     = tmp % nheads;
    int token = tmp / nheads;
    int spos  = token % Sq;

    float c = cs[spos * (HDq / 2) + pair];
    float s = sn[spos * (HDq / 2) + pair];
    float* p = &T[((size_t)token * nheads + h) * HDq + pair * 2];
    float t0 = p[0], t1 = p[1];
    p[0] = t0 * c - t1 * s;
    p[1] = t0 * s + t1 * c;
}

// ---------------------------------------------------------------------------
// fp16 tensor-core flash attention (causal, GQA 4:1).
// CTA: 128 q rows x one (b,h); 8 warps of m16. KV tiles of 64. m16n8k16.
// S: Q frags (ldmatrix) x K (non-trans ldmatrix gives col-major B frags).
// PV: P frags packed from exp'd score frags; V via ldmatrix.trans.
// ---------------------------------------------------------------------------
#define FS 72  // half stride (144B): 8 consecutive rows hit distinct banks

__global__ __launch_bounds__(256) void flash_h(
    const float* __restrict__ Q, const float* __restrict__ K,
    const float* __restrict__ V, __half* __restrict__ O)
{
    __shared__ __half fsm[128 * FS];
    __half* Qs = fsm;               // [128][FS] (tile-load phase only)
    __half* Ks = fsm;               // [64][FS]
    __half* Vs = fsm + 64 * FS;     // [64][FS]

    const int bh  = blockIdx.y;
    const int b   = bh >> 5;
    const int h   = bh & 31;
    const int kvh = h >> 2;
    const int qb  = gridDim.x - 1 - blockIdx.x;   // heavy CTAs first
    const int q0  = qb * 128;

    const int tid = threadIdx.x;
    const int wid = tid >> 5;
    const int lid = tid & 31;
    const int g   = lid >> 2;
    const int tg  = lid & 3;
    const int wq  = wid * 16;

    // ldmatrix lane geometry
    const int a_r = (lid & 15);            // + row base
    const int a_c = 8 * (lid >> 4);
    const int nt_r = (lid & 7) + 8 * (lid >> 4);        // non-trans (K): + n0
    const int nt_c = 8 * ((lid >> 3) & 1);              // + k0
    const int tr_r = (lid & 7) + 8 * ((lid >> 3) & 1);  // trans (V): + k0
    const int tr_c = 8 * (lid >> 4);                    // + n0

    // ---- Load Q tile (scaled fp16) ----
    {
        const int row = tid >> 1, c0 = (tid & 1) * 32;
        const float* src = &Q[((size_t)(b * Sq + q0 + row)) * QDIM + h * HDq + c0];
#pragma unroll
        for (int i = 0; i < 4; i++) {
            float4 v = *(const float4*)(src + 8 * i);
            float4 w = *(const float4*)(src + 8 * i + 4);
            uint4 u;
            u.x = f2h2u(v.x * 0.125f, v.y * 0.125f);
            u.y = f2h2u(v.z * 0.125f, v.w * 0.125f);
            u.z = f2h2u(w.x * 0.125f, w.y * 0.125f);
            u.w = f2h2u(w.z * 0.125f, w.w * 0.125f);
            *(uint4*)&Qs[row * FS + c0 + 8 * i] = u;
        }
    }
    __syncthreads();

    uint32_t qf[4][4];
#pragma unroll
    for (int kc = 0; kc < 4; kc++)
        LDSM4(qf[kc][0], qf[kc][1], qf[kc][2], qf[kc][3],
              s2u(&Qs[(wq + a_r) * FS + kc * 16 + a_c]));

    float oacc[8][4];
#pragma unroll
    for (int nj = 0; nj < 8; nj++)
#pragma unroll
        for (int q = 0; q < 4; q++) oacc[nj][q] = 0.f;
    float m0 = -1e30f, m1 = -1e30f, l0 = 0.f, l1 = 0.f;

    const int ntiles = 2 * qb + 2;
    const int row0 = q0 + wq + g;
    const int row1 = row0 + 8;

    const int kvrow = tid >> 2, kvc = (tid & 3) * 16;

    for (int t = 0; t < ntiles; t++) {
        const int tb = t * 64;
        __syncthreads();

        // ---- Load K/V tiles (fp32 -> fp16) ----
        {
            size_t src = ((size_t)(b * Sq + tb + kvrow)) * KVDIM + kvh * HDq + kvc;
            const float* kp = &K[src];
            const float* vp = &V[src];
#pragma unroll
            for (int i = 0; i < 2; i++) {
                *(uint4*)&Ks[kvrow * FS + kvc + 8 * i] = load8<float>(kp + 8 * i);
                *(uint4*)&Vs[kvrow * FS + kvc + 8 * i] = load8<float>(vp + 8 * i);
            }
        }
        __syncthreads();

        // ---- S = Q @ K^T ----
        float sacc[8][4];
#pragma unroll
        for (int ni = 0; ni < 8; ni++)
#pragma unroll
            for (int q = 0; q < 4; q++) sacc[ni][q] = 0.f;

#pragma unroll
        for (int kc = 0; kc < 4; kc++) {
#pragma unroll
            for (int ng = 0; ng < 4; ng++) {
                uint32_t kf[4];
                LDSM4(kf[0], kf[1], kf[2], kf[3],
                      s2u(&Ks[(ng * 16 + nt_r) * FS + kc * 16 + nt_c]));
                MMA_F16(sacc[2 * ng],     qf[kc][0], qf[kc][1], qf[kc][2], qf[kc][3], kf[0], kf[1]);
                MMA_F16(sacc[2 * ng + 1], qf[kc][0], qf[kc][1], qf[kc][2], qf[kc][3], kf[2], kf[3]);
            }
        }

        // ---- Causal mask ----
        if (tb + 63 > q0 + wq) {
#pragma unroll
            for (int ni = 0; ni < 8; ni++) {
                int key = tb + 8 * ni + 2 * tg;
                if (key > row0)     sacc[ni][0] = -1e30f;
                if (key + 1 > row0) sacc[ni][1] = -1e30f;
                if (key > row1)     sacc[ni][2] = -1e30f;
                if (key + 1 > row1) sacc[ni][3] = -1e30f;
            }
        }

        // ---- Online softmax ----
        float tmax0 = -1e30f, tmax1 = -1e30f;
#pragma unroll
        for (int ni = 0; ni < 8; ni++) {
            tmax0 = fmaxf(tmax0, fmaxf(sacc[ni][0], sacc[ni][1]));
            tmax1 = fmaxf(tmax1, fmaxf(sacc[ni][2], sacc[ni][3]));
        }
        tmax0 = fmaxf(tmax0, __shfl_xor_sync(0xffffffff, tmax0, 1));
        tmax0 = fmaxf(tmax0, __shfl_xor_sync(0xffffffff, tmax0, 2));
        tmax1 = fmaxf(tmax1, __shfl_xor_sync(0xffffffff, tmax1, 1));
        tmax1 = fmaxf(tmax1, __shfl_xor_sync(0xffffffff, tmax1, 2));

        float nm0 = fmaxf(m0, tmax0);
        float nm1 = fmaxf(m1, tmax1);
        float corr0 = __expf(m0 - nm0);
        float corr1 = __expf(m1 - nm1);

        float pv[8][4];
        float rs0 = 0.f, rs1 = 0.f;
#pragma unroll
        for (int ni = 0; ni < 8; ni++) {
            pv[ni][0] = __expf(sacc[ni][0] - nm0);
            pv[ni][1] = __expf(sacc[ni][1] - nm0);
            pv[ni][2] = __expf(sacc[ni][2] - nm1);
            pv[ni][3] = __expf(sacc[ni][3] - nm1);
            rs0 += pv[ni][0] + pv[ni][1];
            rs1 += pv[ni][2] + pv[ni][3];
        }
        rs0 += __shfl_xor_sync(0xffffffff, rs0, 1);
        rs0 += __shfl_xor_sync(0xffffffff, rs0, 2);
        rs1 += __shfl_xor_sync(0xffffffff, rs1, 1);
        rs1 += __shfl_xor_sync(0xffffffff, rs1, 2);

        l0 = l0 * corr0 + rs0;
        l1 = l1 * corr1 + rs1;
#pragma unroll
        for (int nj = 0; nj < 8; nj++) {
            oacc[nj][0] *= corr0;
            oacc[nj][1] *= corr0;
            oacc[nj][2] *= corr1;
            oacc[nj][3] *= corr1;
        }
        m0 = nm0;
        m1 = nm1;

        // ---- O += P @ V ----
#pragma unroll
        for (int kc = 0; kc < 4; kc++) {   // key-16 groups
            uint32_t a0 = f2h2u(pv[2 * kc][0], pv[2 * kc][1]);
            uint32_t a1 = f2h2u(pv[2 * kc][2], pv[2 * kc][3]);
            uint32_t a2 = f2h2u(pv[2 * kc + 1][0], pv[2 * kc + 1][1]);
            uint32_t a3 = f2h2u(pv[2 * kc + 1][2], pv[2 * kc + 1][3]);
#pragma unroll
            for (int ng = 0; ng < 4; ng++) {   // d-blocks (pairs of n8)
                uint32_t vf[4];
                LDSM4T(vf[0], vf[1], vf[2], vf[3],
                       s2u(&Vs[(kc * 16 + tr_r) * FS + ng * 16 + tr_c]));
                MMA_F16(oacc[2 * ng],     a0, a1, a2, a3, vf[0], vf[1]);
                MMA_F16(oacc[2 * ng + 1], a0, a1, a2, a3, vf[2], vf[3]);
            }
        }
    }

    // ---- Normalize and write (fp16) ----
    float inv0 = 1.f / l0;
    float inv1 = 1.f / l1;
    const size_t tok0 = (size_t)b * Sq + row0;
#pragma unroll
    for (int nj = 0; nj < 8; nj++) {
        const int col = h * HDq + 8 * nj + 2 * tg;
        *(__half2*)&O[tok0 * QDIM + col] =
            __floats2half2_rn(oacc[nj][0] * inv0, oacc[nj][1] * inv0);
        *(__half2*)&O[(tok0 + 8) * QDIM + col] =
            __floats2half2_rn(oacc[nj][2] * inv1, oacc[nj][3] * inv1);
    }
}

// ---------------------------------------------------------------------------
// Launch
// ---------------------------------------------------------------------------
extern "C" void kernel_launch(void* const* d_in, const int* in_sizes, int n_in,
                              void* d_out, int out_size)
{
    const float* x   = (const float*)d_in[0];
    const float* cs  = (const float*)d_in[1];
    const float* sn  = (const float*)d_in[2];
    const float* Wq  = (const float*)d_in[3];
    const float* Wk  = (const float*)d_in[4];
    const float* Wv  = (const float*)d_in[5];
    const float* Wo  = (const float*)d_in[6];
    float* out = (float*)d_out;

    float *Q, *K, *V;
    __half* O;
    cudaGetSymbolAddress((void**)&Q, g_Q);
    cudaGetSymbolAddress((void**)&K, g_K);
    cudaGetSymbolAddress((void**)&V, g_V);
    cudaGetSymbolAddress((void**)&O, g_O);

    // QKV projections (fp16 mma, fp32 accumulate)
    gemm_h<float><<<dim3(QDIM / 128, NTOK / 128), 256>>>(x, Wq, Q, QDIM, DIMq);
    gemm_h<float><<<dim3(KVDIM / 128, NTOK / 128), 256>>>(x, Wk, K, KVDIM, DIMq);
    gemm_h<float><<<dim3(KVDIM / 128, NTOK / 128), 256>>>(x, Wv, V, KVDIM, DIMq);

    // RoPE (fp32)
    {
        int nq = NTOK * NHq * (HDq / 2);
        rope_kernel<<<(nq + 255) / 256, 256>>>(Q, cs, sn, NHq);
        int nk = NTOK * NKVq * (HDq / 2);
        rope_kernel<<<(nk + 255) / 256, 256>>>(K, cs, sn, NKVq);
    }

    // fp16 tensor-core flash attention
    flash_h<<<dim3(Sq / 128, Bq * NHq), 256>>>(Q, K, V, O);

    // Output projection (A = fp16 O)
    gemm_h<__half><<<dim3(DIMq / 128, NTOK / 128), 256>>>(O, Wo, out, DIMq, QDIM);
}

// round 8
// speedup vs baseline: 6.8011x; 1.5347x over previous
#include <cuda_runtime.h>
#include <cuda_fp16.h>
#include <cstdint>

// Problem constants
#define Bq 2
#define Sq 2048
#define DIMq 2048
#define NHq 32
#define NKVq 8
#define HDq 64
#define NTOK (Bq * Sq)          // 4096
#define QDIM (NHq * HDq)        // 2048
#define KVDIM (NKVq * HDq)      // 512

// ---------------------------------------------------------------------------
// Scratch (__device__ globals; no allocation allowed)
// ---------------------------------------------------------------------------
__device__ __align__(16) __half g_Xh[NTOK * DIMq];    // 16 MB  fp16 x
__device__ __align__(16) __half g_Wqh[DIMq * QDIM];   // 8 MB
__device__ __align__(16) __half g_Wkh[DIMq * KVDIM];  // 2 MB
__device__ __align__(16) __half g_Wvh[DIMq * KVDIM];  // 2 MB
__device__ __align__(16) __half g_Woh[QDIM * DIMq];   // 8 MB
__device__ __align__(16) __half g_Q[NTOK * QDIM];     // 16 MB (post-RoPE fp16)
__device__ __align__(16) __half g_K[NTOK * KVDIM];    // 4 MB
__device__ __align__(16) __half g_V[NTOK * KVDIM];    // 4 MB
__device__ __align__(16) __half g_O[NTOK * QDIM];     // 16 MB

__device__ __forceinline__ uint32_t s2u(const void* p) {
    return (uint32_t)__cvta_generic_to_shared(p);
}
__device__ __forceinline__ uint32_t f2h2u(float x, float y) {
    __half2 h = __floats2half2_rn(x, y);
    return *(uint32_t*)&h;
}

#define LDSM4(r0, r1, r2, r3, addr)                                          \
    asm volatile("ldmatrix.sync.aligned.m8n8.x4.shared.b16 {%0,%1,%2,%3}, [%4];" \
                 : "=r"(r0), "=r"(r1), "=r"(r2), "=r"(r3) : "r"(addr))
#define LDSM4T(r0, r1, r2, r3, addr)                                         \
    asm volatile("ldmatrix.sync.aligned.m8n8.x4.trans.shared.b16 {%0,%1,%2,%3}, [%4];" \
                 : "=r"(r0), "=r"(r1), "=r"(r2), "=r"(r3) : "r"(addr))
#define MMA_F16(c, a0, a1, a2, a3, b0, b1)                                   \
    asm volatile(                                                            \
        "mma.sync.aligned.m16n8k16.row.col.f32.f16.f16.f32 "                 \
        "{%0,%1,%2,%3}, {%4,%5,%6,%7}, {%8,%9}, {%0,%1,%2,%3};"              \
        : "+f"((c)[0]), "+f"((c)[1]), "+f"((c)[2]), "+f"((c)[3])             \
        : "r"(a0), "r"(a1), "r"(a2), "r"(a3), "r"(b0), "r"(b1))
#define CP16(dst, src)                                                       \
    asm volatile("cp.async.ca.shared.global [%0], [%1], 16;"                 \
                 :: "r"(dst), "l"(src) : "memory")
#define CP_COMMIT() asm volatile("cp.async.commit_group;" ::: "memory")
#define CP_WAIT1()  asm volatile("cp.async.wait_group 1;" ::: "memory")
#define CP_WAIT0()  asm volatile("cp.async.wait_group 0;" ::: "memory")

// ---------------------------------------------------------------------------
// fp32 -> fp16 bulk convert (8 elems/thread)
// ---------------------------------------------------------------------------
__global__ void cvt_h(const float* __restrict__ src, __half* __restrict__ dst, int n)
{
    int i = (blockIdx.x * blockDim.x + threadIdx.x) * 8;
    if (i >= n) return;
    float4 a = *(const float4*)(src + i);
    float4 b = *(const float4*)(src + i + 4);
    uint4 u;
    u.x = f2h2u(a.x, a.y);
    u.y = f2h2u(a.z, a.w);
    u.z = f2h2u(b.x, b.y);
    u.w = f2h2u(b.z, b.w);
    *(uint4*)(dst + i) = u;
}

// ---------------------------------------------------------------------------
// fp16 GEMM with fused epilogue: C[M,N] = A[M,K] @ B[K,N], A/B fp16 gmem.
// EPI: 0 = fp32 out, 1 = fp16 out, 2 = fp16 out with fused RoPE.
// CTA 128x128, BK=16, 8 warps (2x4) of 64x32 tiles, 2-stage cp.async pipe.
// ---------------------------------------------------------------------------
template <int EPI>
__global__ __launch_bounds__(256, 2) void gemm_h(
    const __half* __restrict__ A, const __half* __restrict__ B,
    void* __restrict__ Cv, int N, int K,
    const float* __restrict__ cs, const float* __restrict__ sn)
{
    __shared__ __half As[2][128][24];   // [m][k] pad 16->24
    __shared__ __half Bs[2][16][136];   // [k][n] pad 128->136

    const int tid = threadIdx.x;
    const int wid = tid >> 5;
    const int lid = tid & 31;
    const int g   = lid >> 2;
    const int tg  = lid & 3;

    const int brow = blockIdx.y * 128;
    const int bcol = blockIdx.x * 128;
    const int wm = (wid & 1) * 64;
    const int wn = (wid >> 1) * 32;

    const int ar = tid >> 1, ac = (tid & 1) * 8;
    const int brr = tid >> 4, bcc = (tid & 15) * 8;
    const __half* Ap = A + (size_t)(brow + ar) * K + ac;
    const __half* Bp = B + (size_t)brr * N + bcol + bcc;

    const int a_r = wm + (lid & 15);
    const int a_c = 8 * (lid >> 4);
    const int b_k = (lid & 7) + 8 * ((lid >> 3) & 1);
    const int b_n = 8 * (lid >> 4);

    float acc[4][4][4];
#pragma unroll
    for (int mi = 0; mi < 4; mi++)
#pragma unroll
        for (int ni = 0; ni < 4; ni++)
#pragma unroll
            for (int q = 0; q < 4; q++) acc[mi][ni][q] = 0.f;

    const int NC = K >> 4;

    // Prologue: async-copy chunk 0 into buf 0
    CP16(s2u(&As[0][ar][ac]), Ap);
    CP16(s2u(&Bs[0][brr][bcc]), Bp);
    CP_COMMIT();

    for (int kc = 0; kc < NC; kc++) {
        const int cur = kc & 1;
        const bool has_next = (kc + 1) < NC;
        if (has_next) {
            CP16(s2u(&As[cur ^ 1][ar][ac]), Ap + ((kc + 1) << 4));
            CP16(s2u(&Bs[cur ^ 1][brr][bcc]), Bp + (size_t)((kc + 1) << 4) * N);
            CP_COMMIT();
            CP_WAIT1();
        } else {
            CP_WAIT0();
        }
        __syncthreads();

        uint32_t af[4][4];
#pragma unroll
        for (int mi = 0; mi < 4; mi++)
            LDSM4(af[mi][0], af[mi][1], af[mi][2], af[mi][3],
                  s2u(&As[cur][a_r + mi * 16][a_c]));

        uint32_t bf[4][2];
#pragma unroll
        for (int nq = 0; nq < 2; nq++)
            LDSM4T(bf[2 * nq][0], bf[2 * nq][1], bf[2 * nq + 1][0], bf[2 * nq + 1][1],
                   s2u(&Bs[cur][b_k][wn + nq * 16 + b_n]));

#pragma unroll
        for (int mi = 0; mi < 4; mi++)
#pragma unroll
            for (int ni = 0; ni < 4; ni++)
                MMA_F16(acc[mi][ni], af[mi][0], af[mi][1], af[mi][2], af[mi][3],
                        bf[ni][0], bf[ni][1]);

        __syncthreads();  // all reads of cur done before it is re-filled
    }

    // ---- Epilogue ----
#pragma unroll
    for (int mi = 0; mi < 4; mi++) {
#pragma unroll
        for (int ni = 0; ni < 4; ni++) {
            const int row = brow + wm + mi * 16 + g;
            const int col = bcol + wn + ni * 8 + 2 * tg;
            if (EPI == 0) {
                float* C = (float*)Cv;
                *(float2*)&C[(size_t)row * N + col] =
                    make_float2(acc[mi][ni][0], acc[mi][ni][1]);
                *(float2*)&C[(size_t)(row + 8) * N + col] =
                    make_float2(acc[mi][ni][2], acc[mi][ni][3]);
            } else if (EPI == 1) {
                __half* C = (__half*)Cv;
                *(__half2*)&C[(size_t)row * N + col] =
                    __floats2half2_rn(acc[mi][ni][0], acc[mi][ni][1]);
                *(__half2*)&C[(size_t)(row + 8) * N + col] =
                    __floats2half2_rn(acc[mi][ni][2], acc[mi][ni][3]);
            } else {
                __half* C = (__half*)Cv;
                const int pair = (col & 63) >> 1;
                const int sp0 = row & (Sq - 1);
                const int sp1 = (row + 8) & (Sq - 1);
                float c0 = cs[sp0 * 32 + pair], s0 = sn[sp0 * 32 + pair];
                float c1 = cs[sp1 * 32 + pair], s1 = sn[sp1 * 32 + pair];
                float x0 = acc[mi][ni][0] * c0 - acc[mi][ni][1] * s0;
                float x1 = acc[mi][ni][0] * s0 + acc[mi][ni][1] * c0;
                float y0 = acc[mi][ni][2] * c1 - acc[mi][ni][3] * s1;
                float y1 = acc[mi][ni][2] * s1 + acc[mi][ni][3] * c1;
                *(__half2*)&C[(size_t)row * N + col] = __floats2half2_rn(x0, x1);
                *(__half2*)&C[(size_t)(row + 8) * N + col] = __floats2half2_rn(y0, y1);
            }
        }
    }
}

// ---------------------------------------------------------------------------
// fp16 tensor-core flash attention (causal, GQA 4:1), fp16 in/out,
// 2-stage cp.async K/V pipeline. CTA: 128 q rows x (b,h); 8 warps of m16.
// ---------------------------------------------------------------------------
#define FS 72  // half stride (144B): conflict-free ldmatrix

__global__ __launch_bounds__(256) void flash_h(
    const __half* __restrict__ Q, const __half* __restrict__ K,
    const __half* __restrict__ V, __half* __restrict__ O)
{
    __shared__ __half fsm[2][128 * FS];   // per buf: K[64][FS], V[64][FS]
    __half* Qs = fsm[0];                  // overlay during Q-frag build

    const int bh  = blockIdx.y;
    const int b   = bh >> 5;
    const int h   = bh & 31;
    const int kvh = h >> 2;
    const int qb  = gridDim.x - 1 - blockIdx.x;   // heavy CTAs first
    const int q0  = qb * 128;

    const int tid = threadIdx.x;
    const int wid = tid >> 5;
    const int lid = tid & 31;
    const int g   = lid >> 2;
    const int tg  = lid & 3;
    const int wq  = wid * 16;

    const int a_r = (lid & 15);
    const int a_c = 8 * (lid >> 4);
    const int nt_r = (lid & 7) + 8 * (lid >> 4);
    const int nt_c = 8 * ((lid >> 3) & 1);
    const int tr_r = (lid & 7) + 8 * ((lid >> 3) & 1);
    const int tr_c = 8 * (lid >> 4);

    // ---- Load Q tile (fp16, exact x0.125 scale) ----
    // Each of 256 threads: one row half (32 halves) = 4 x uint4 (8 halves each).
    {
        const int row = tid >> 1, c0 = (tid & 1) * 32;
        const __half* src = &Q[((size_t)(b * Sq + q0 + row)) * QDIM + h * HDq + c0];
        const __half2 hs = __floats2half2_rn(0.125f, 0.125f);
#pragma unroll
        for (int i = 0; i < 4; i++) {
            uint4 u = *(const uint4*)(src + 8 * i);
            __half2* hp = (__half2*)&u;
#pragma unroll
            for (int j = 0; j < 4; j++) hp[j] = __hmul2(hp[j], hs);
            *(uint4*)&Qs[row * FS + c0 + 8 * i] = u;
        }
    }
    __syncthreads();

    uint32_t qf[4][4];
#pragma unroll
    for (int kc = 0; kc < 4; kc++)
        LDSM4(qf[kc][0], qf[kc][1], qf[kc][2], qf[kc][3],
              s2u(&Qs[(wq + a_r) * FS + kc * 16 + a_c]));
    __syncthreads();  // Q frags in regs; smem reusable

    float oacc[8][4];
#pragma unroll
    for (int nj = 0; nj < 8; nj++)
#pragma unroll
        for (int q = 0; q < 4; q++) oacc[nj][q] = 0.f;
    float m0 = -1e30f, m1 = -1e30f, l0 = 0.f, l1 = 0.f;

    const int ntiles = 2 * qb + 2;
    const int row0 = q0 + wq + g;
    const int row1 = row0 + 8;

    const int kvrow = tid >> 2, kvc = (tid & 3) * 16;
    const size_t kvbase = ((size_t)b * Sq + kvrow) * KVDIM + kvh * HDq + kvc;

    // Prologue: tile 0 -> buf 0
    {
        __half* Ks = fsm[0];
        __half* Vs = fsm[0] + 64 * FS;
        const __half* kp = K + kvbase;
        const __half* vp = V + kvbase;
#pragma unroll
        for (int i = 0; i < 2; i++) {
            CP16(s2u(&Ks[kvrow * FS + kvc + 8 * i]), kp + 8 * i);
            CP16(s2u(&Vs[kvrow * FS + kvc + 8 * i]), vp + 8 * i);
        }
        CP_COMMIT();
    }

    for (int t = 0; t < ntiles; t++) {
        const int cur = t & 1;
        const bool has_next = (t + 1) < ntiles;
        if (has_next) {
            __half* Ks = fsm[cur ^ 1];
            __half* Vs = fsm[cur ^ 1] + 64 * FS;
            const size_t off = kvbase + (size_t)(t + 1) * 64 * KVDIM;
            const __half* kp = K + off;
            const __half* vp = V + off;
#pragma unroll
            for (int i = 0; i < 2; i++) {
                CP16(s2u(&Ks[kvrow * FS + kvc + 8 * i]), kp + 8 * i);
                CP16(s2u(&Vs[kvrow * FS + kvc + 8 * i]), vp + 8 * i);
            }
            CP_COMMIT();
            CP_WAIT1();
        } else {
            CP_WAIT0();
        }
        __syncthreads();

        const __half* Ks = fsm[cur];
        const __half* Vs = fsm[cur] + 64 * FS;
        const int tb = t * 64;

        // ---- S = Q @ K^T ----
        float sacc[8][4];
#pragma unroll
        for (int ni = 0; ni < 8; ni++)
#pragma unroll
            for (int q = 0; q < 4; q++) sacc[ni][q] = 0.f;

#pragma unroll
        for (int kc = 0; kc < 4; kc++) {
#pragma unroll
            for (int ng = 0; ng < 4; ng++) {
                uint32_t kf[4];
                LDSM4(kf[0], kf[1], kf[2], kf[3],
                      s2u(&Ks[(ng * 16 + nt_r) * FS + kc * 16 + nt_c]));
                MMA_F16(sacc[2 * ng],     qf[kc][0], qf[kc][1], qf[kc][2], qf[kc][3], kf[0], kf[1]);
                MMA_F16(sacc[2 * ng + 1], qf[kc][0], qf[kc][1], qf[kc][2], qf[kc][3], kf[2], kf[3]);
            }
        }

        // ---- Causal mask ----
        if (tb + 63 > q0 + wq) {
#pragma unroll
            for (int ni = 0; ni < 8; ni++) {
                int key = tb + 8 * ni + 2 * tg;
                if (key > row0)     sacc[ni][0] = -1e30f;
                if (key + 1 > row0) sacc[ni][1] = -1e30f;
                if (key > row1)     sacc[ni][2] = -1e30f;
                if (key + 1 > row1) sacc[ni][3] = -1e30f;
            }
        }

        // ---- Online softmax ----
        float tmax0 = -1e30f, tmax1 = -1e30f;
#pragma unroll
        for (int ni = 0; ni < 8; ni++) {
            tmax0 = fmaxf(tmax0, fmaxf(sacc[ni][0], sacc[ni][1]));
            tmax1 = fmaxf(tmax1, fmaxf(sacc[ni][2], sacc[ni][3]));
        }
        tmax0 = fmaxf(tmax0, __shfl_xor_sync(0xffffffff, tmax0, 1));
        tmax0 = fmaxf(tmax0, __shfl_xor_sync(0xffffffff, tmax0, 2));
        tmax1 = fmaxf(tmax1, __shfl_xor_sync(0xffffffff, tmax1, 1));
        tmax1 = fmaxf(tmax1, __shfl_xor_sync(0xffffffff, tmax1, 2));

        float nm0 = fmaxf(m0, tmax0);
        float nm1 = fmaxf(m1, tmax1);
        float corr0 = __expf(m0 - nm0);
        float corr1 = __expf(m1 - nm1);

        float pv[8][4];
        float rs0 = 0.f, rs1 = 0.f;
#pragma unroll
        for (int ni = 0; ni < 8; ni++) {
            pv[ni][0] = __expf(sacc[ni][0] - nm0);
            pv[ni][1] = __expf(sacc[ni][1] - nm0);
            pv[ni][2] = __expf(sacc[ni][2] - nm1);
            pv[ni][3] = __expf(sacc[ni][3] - nm1);
            rs0 += pv[ni][0] + pv[ni][1];
            rs1 += pv[ni][2] + pv[ni][3];
        }
        rs0 += __shfl_xor_sync(0xffffffff, rs0, 1);
        rs0 += __shfl_xor_sync(0xffffffff, rs0, 2);
        rs1 += __shfl_xor_sync(0xffffffff, rs1, 1);
        rs1 += __shfl_xor_sync(0xffffffff, rs1, 2);

        l0 = l0 * corr0 + rs0;
        l1 = l1 * corr1 + rs1;
#pragma unroll
        for (int nj = 0; nj < 8; nj++) {
            oacc[nj][0] *= corr0;
            oacc[nj][1] *= corr0;
            oacc[nj][2] *= corr1;
            oacc[nj][3] *= corr1;
        }
        m0 = nm0;
        m1 = nm1;

        // ---- O += P @ V ----
#pragma unroll
        for (int kc = 0; kc < 4; kc++) {
            uint32_t a0 = f2h2u(pv[2 * kc][0], pv[2 * kc][1]);
            uint32_t a1 = f2h2u(pv[2 * kc][2], pv[2 * kc][3]);
            uint32_t a2 = f2h2u(pv[2 * kc + 1][0], pv[2 * kc + 1][1]);
            uint32_t a3 = f2h2u(pv[2 * kc + 1][2], pv[2 * kc + 1][3]);
#pragma unroll
            for (int ng = 0; ng < 4; ng++) {
                uint32_t vf[4];
                LDSM4T(vf[0], vf[1], vf[2], vf[3],
                       s2u(&Vs[(kc * 16 + tr_r) * FS + ng * 16 + tr_c]));
                MMA_F16(oacc[2 * ng],     a0, a1, a2, a3, vf[0], vf[1]);
                MMA_F16(oacc[2 * ng + 1], a0, a1, a2, a3, vf[2], vf[3]);
            }
        }
        __syncthreads();
    }

    // ---- Normalize and write (fp16) ----
    float inv0 = 1.f / l0;
    float inv1 = 1.f / l1;
    const size_t tok0 = (size_t)b * Sq + row0;
#pragma unroll
    for (int nj = 0; nj < 8; nj++) {
        const int col = h * HDq + 8 * nj + 2 * tg;
        *(__half2*)&O[tok0 * QDIM + col] =
            __floats2half2_rn(oacc[nj][0] * inv0, oacc[nj][1] * inv0);
        *(__half2*)&O[(tok0 + 8) * QDIM + col] =
            __floats2half2_rn(oacc[nj][2] * inv1, oacc[nj][3] * inv1);
    }
}

// ---------------------------------------------------------------------------
// Launch
// ---------------------------------------------------------------------------
extern "C" void kernel_launch(void* const* d_in, const int* in_sizes, int n_in,
                              void* d_out, int out_size)
{
    const float* x   = (const float*)d_in[0];
    const float* cs  = (const float*)d_in[1];
    const float* sn  = (const float*)d_in[2];
    const float* Wq  = (const float*)d_in[3];
    const float* Wk  = (const float*)d_in[4];
    const float* Wv  = (const float*)d_in[5];
    const float* Wo  = (const float*)d_in[6];
    float* out = (float*)d_out;

    __half *Xh, *Wqh, *Wkh, *Wvh, *Woh, *Q, *K, *V, *O;
    cudaGetSymbolAddress((void**)&Xh, g_Xh);
    cudaGetSymbolAddress((void**)&Wqh, g_Wqh);
    cudaGetSymbolAddress((void**)&Wkh, g_Wkh);
    cudaGetSymbolAddress((void**)&Wvh, g_Wvh);
    cudaGetSymbolAddress((void**)&Woh, g_Woh);
    cudaGetSymbolAddress((void**)&Q, g_Q);
    cudaGetSymbolAddress((void**)&K, g_K);
    cudaGetSymbolAddress((void**)&V, g_V);
    cudaGetSymbolAddress((void**)&O, g_O);

    // fp32 -> fp16 staging
    cvt_h<<<NTOK * DIMq / 8 / 256, 256>>>(x, Xh, NTOK * DIMq);
    cvt_h<<<DIMq * QDIM / 8 / 256, 256>>>(Wq, Wqh, DIMq * QDIM);
    cvt_h<<<DIMq * KVDIM / 8 / 256, 256>>>(Wk, Wkh, DIMq * KVDIM);
    cvt_h<<<DIMq * KVDIM / 8 / 256, 256>>>(Wv, Wvh, DIMq * KVDIM);
    cvt_h<<<QDIM * DIMq / 8 / 256, 256>>>(Wo, Woh, QDIM * DIMq);

    // Projections with fused RoPE (Q,K) / plain fp16 (V)
    gemm_h<2><<<dim3(QDIM / 128, NTOK / 128), 256>>>(Xh, Wqh, Q, QDIM, DIMq, cs, sn);
    gemm_h<2><<<dim3(KVDIM / 128, NTOK / 128), 256>>>(Xh, Wkh, K, KVDIM, DIMq, cs, sn);
    gemm_h<1><<<dim3(KVDIM / 128, NTOK / 128), 256>>>(Xh, Wvh, V, KVDIM, DIMq, cs, sn);

    // fp16 flash attention
    flash_h<<<dim3(Sq / 128, Bq * NHq), 256>>>(Q, K, V, O);

    // Output projection (fp32 out)
    gemm_h<0><<<dim3(DIMq / 128, NTOK / 128), 256>>>(O, Woh, out, DIMq, QDIM, cs, sn);
}

// round 9
// speedup vs baseline: 6.9542x; 1.0225x over previous
#include <cuda_runtime.h>
#include <cuda_fp16.h>
#include <cstdint>

// Problem constants
#define Bq 2
#define Sq 2048
#define DIMq 2048
#define NHq 32
#define NKVq 8
#define HDq 64
#define NTOK (Bq * Sq)          // 4096
#define QDIM (NHq * HDq)        // 2048
#define KVDIM (NKVq * HDq)      // 512
#define NCAT (QDIM + 2 * KVDIM) // 3072

// ---------------------------------------------------------------------------
// Scratch (__device__ globals; no allocation allowed)
// ---------------------------------------------------------------------------
__device__ __align__(16) __half g_Xh[NTOK * DIMq];     // 16 MB fp16 x
__device__ __align__(16) __half g_Wcat[DIMq * NCAT];   // 12 MB [K, Nq|Nk|Nv]
__device__ __align__(16) __half g_Woh[QDIM * DIMq];    // 8 MB
__device__ __align__(16) __half g_Q[NTOK * QDIM];      // 16 MB (post-RoPE)
__device__ __align__(16) __half g_K[NTOK * KVDIM];     // 4 MB
__device__ __align__(16) __half g_V[NTOK * KVDIM];     // 4 MB
__device__ __align__(16) __half g_O[NTOK * QDIM];      // 16 MB

__device__ __forceinline__ uint32_t s2u(const void* p) {
    return (uint32_t)__cvta_generic_to_shared(p);
}
__device__ __forceinline__ uint32_t f2h2u(float x, float y) {
    __half2 h = __floats2half2_rn(x, y);
    return *(uint32_t*)&h;
}

#define LDSM4(r0, r1, r2, r3, addr)                                          \
    asm volatile("ldmatrix.sync.aligned.m8n8.x4.shared.b16 {%0,%1,%2,%3}, [%4];" \
                 : "=r"(r0), "=r"(r1), "=r"(r2), "=r"(r3) : "r"(addr))
#define LDSM4T(r0, r1, r2, r3, addr)                                         \
    asm volatile("ldmatrix.sync.aligned.m8n8.x4.trans.shared.b16 {%0,%1,%2,%3}, [%4];" \
                 : "=r"(r0), "=r"(r1), "=r"(r2), "=r"(r3) : "r"(addr))
#define MMA_F16(c, a0, a1, a2, a3, b0, b1)                                   \
    asm volatile(                                                            \
        "mma.sync.aligned.m16n8k16.row.col.f32.f16.f16.f32 "                 \
        "{%0,%1,%2,%3}, {%4,%5,%6,%7}, {%8,%9}, {%0,%1,%2,%3};"              \
        : "+f"((c)[0]), "+f"((c)[1]), "+f"((c)[2]), "+f"((c)[3])             \
        : "r"(a0), "r"(a1), "r"(a2), "r"(a3), "r"(b0), "r"(b1))
#define CP16(dst, src)                                                       \
    asm volatile("cp.async.ca.shared.global [%0], [%1], 16;"                 \
                 :: "r"(dst), "l"(src) : "memory")
#define CP_COMMIT() asm volatile("cp.async.commit_group;" ::: "memory")
#define CP_WAIT1()  asm volatile("cp.async.wait_group 1;" ::: "memory")
#define CP_WAIT0()  asm volatile("cp.async.wait_group 0;" ::: "memory")

// ---------------------------------------------------------------------------
// fp32 -> fp16 converts (8 elems/thread); _cat writes into g_Wcat columns
// ---------------------------------------------------------------------------
__global__ void cvt_h(const float* __restrict__ src, __half* __restrict__ dst, int n)
{
    int i = (blockIdx.x * blockDim.x + threadIdx.x) * 8;
    if (i >= n) return;
    float4 a = *(const float4*)(src + i);
    float4 b = *(const float4*)(src + i + 4);
    uint4 u;
    u.x = f2h2u(a.x, a.y);
    u.y = f2h2u(a.z, a.w);
    u.z = f2h2u(b.x, b.y);
    u.w = f2h2u(b.z, b.w);
    *(uint4*)(dst + i) = u;
}

__global__ void cvt_cat(const float* __restrict__ src, __half* __restrict__ dst,
                        int srcN, int dstOff, int n)
{
    int i = (blockIdx.x * blockDim.x + threadIdx.x) * 8;
    if (i >= n) return;
    int row = i / srcN, col = i % srcN;
    float4 a = *(const float4*)(src + i);
    float4 b = *(const float4*)(src + i + 4);
    uint4 u;
    u.x = f2h2u(a.x, a.y);
    u.y = f2h2u(a.z, a.w);
    u.z = f2h2u(b.x, b.y);
    u.w = f2h2u(b.z, b.w);
    *(uint4*)(dst + (size_t)row * NCAT + dstOff + col) = u;
}

// ---------------------------------------------------------------------------
// Shared GEMM mainloop: BK=32, CTA 128x128, 8 warps (2x4) of 64x32.
// Produces acc[4][4][4]. A/B fp16 gmem, 2-stage cp.async pipeline.
// ---------------------------------------------------------------------------
struct GemmCtx {
    int wm, wn, g, tg;
    float acc[4][4][4];
};

__device__ __forceinline__ void gemm_mainloop(
    const __half* __restrict__ A, const __half* __restrict__ B,
    int N, int K, int brow, int bcol,
    __half (*As)[128][40], __half (*Bs)[32][136], GemmCtx& cx)
{
    const int tid = threadIdx.x;
    const int wid = tid >> 5;
    const int lid = tid & 31;
    cx.g  = lid >> 2;
    cx.tg = lid & 3;
    cx.wm = (wid & 1) * 64;
    cx.wn = (wid >> 1) * 32;

    // Loaders: A row per 2 threads (2x CP16); B row per 8 threads (2x CP16).
    const int ar = tid >> 1, ac = (tid & 1) * 16;
    const int brr = tid >> 3, bcc = (tid & 7) * 16;
    const __half* Ap = A + (size_t)(brow + ar) * K + ac;
    const __half* Bp = B + (size_t)brr * N + bcol + bcc;

    const int a_r = cx.wm + (lid & 15);
    const int a_c = 8 * (lid >> 4);
    const int b_k = (lid & 7) + 8 * ((lid >> 3) & 1);
    const int b_n = 8 * (lid >> 4);

#pragma unroll
    for (int mi = 0; mi < 4; mi++)
#pragma unroll
        for (int ni = 0; ni < 4; ni++)
#pragma unroll
            for (int q = 0; q < 4; q++) cx.acc[mi][ni][q] = 0.f;

    const int NC = K >> 5;

    CP16(s2u(&As[0][ar][ac]), Ap);
    CP16(s2u(&As[0][ar][ac + 8]), Ap + 8);
    CP16(s2u(&Bs[0][brr][bcc]), Bp);
    CP16(s2u(&Bs[0][brr][bcc + 8]), Bp + 8);
    CP_COMMIT();

    for (int kc = 0; kc < NC; kc++) {
        const int cur = kc & 1;
        const bool has_next = (kc + 1) < NC;
        if (has_next) {
            const __half* An = Ap + ((kc + 1) << 5);
            const __half* Bn = Bp + (size_t)((kc + 1) << 5) * N;
            CP16(s2u(&As[cur ^ 1][ar][ac]), An);
            CP16(s2u(&As[cur ^ 1][ar][ac + 8]), An + 8);
            CP16(s2u(&Bs[cur ^ 1][brr][bcc]), Bn);
            CP16(s2u(&Bs[cur ^ 1][brr][bcc + 8]), Bn + 8);
            CP_COMMIT();
            CP_WAIT1();
        } else {
            CP_WAIT0();
        }
        __syncthreads();

#pragma unroll
        for (int ks = 0; ks < 2; ks++) {
            uint32_t af[4][4];
#pragma unroll
            for (int mi = 0; mi < 4; mi++)
                LDSM4(af[mi][0], af[mi][1], af[mi][2], af[mi][3],
                      s2u(&As[cur][a_r + mi * 16][ks * 16 + a_c]));
            uint32_t bf[4][2];
#pragma unroll
            for (int nq = 0; nq < 2; nq++)
                LDSM4T(bf[2 * nq][0], bf[2 * nq][1],
                       bf[2 * nq + 1][0], bf[2 * nq + 1][1],
                       s2u(&Bs[cur][ks * 16 + b_k][cx.wn + nq * 16 + b_n]));
#pragma unroll
            for (int mi = 0; mi < 4; mi++)
#pragma unroll
                for (int ni = 0; ni < 4; ni++)
                    MMA_F16(cx.acc[mi][ni], af[mi][0], af[mi][1], af[mi][2], af[mi][3],
                            bf[ni][0], bf[ni][1]);
        }
        __syncthreads();
    }
}

// ---------------------------------------------------------------------------
// Fused QKV projection: X[4096,2048] @ Wcat[2048,3072] -> Q (RoPE), K (RoPE),
// V (plain), all fp16. Region is CTA-uniform (128 | 2048, 2560).
// ---------------------------------------------------------------------------
__global__ __launch_bounds__(256, 2) void gemm_qkv(
    const __half* __restrict__ X, const __half* __restrict__ Wc,
    __half* __restrict__ Q, __half* __restrict__ K, __half* __restrict__ V,
    const float* __restrict__ cs, const float* __restrict__ sn)
{
    __shared__ __half As[2][128][40];
    __shared__ __half Bs[2][32][136];

    const int brow = blockIdx.y * 128;
    const int bcol = blockIdx.x * 128;

    GemmCtx cx;
    gemm_mainloop(X, Wc, NCAT, DIMq, brow, bcol, As, Bs, cx);

    __half* C;
    int coff, Nout;
    bool rope;
    if (bcol < QDIM)              { C = Q; coff = 0;            Nout = QDIM;  rope = true;  }
    else if (bcol < QDIM + KVDIM) { C = K; coff = QDIM;         Nout = KVDIM; rope = true;  }
    else                          { C = V; coff = QDIM + KVDIM; Nout = KVDIM; rope = false; }

#pragma unroll
    for (int mi = 0; mi < 4; mi++) {
#pragma unroll
        for (int ni = 0; ni < 4; ni++) {
            const int row = brow + cx.wm + mi * 16 + cx.g;
            const int col = bcol - coff + cx.wn + ni * 8 + 2 * cx.tg;
            float* a = cx.acc[mi][ni];
            if (rope) {
                const int pair = (col & 63) >> 1;
                const int sp0 = row & (Sq - 1);
                const int sp1 = (row + 8) & (Sq - 1);
                float c0 = cs[sp0 * 32 + pair], s0 = sn[sp0 * 32 + pair];
                float c1 = cs[sp1 * 32 + pair], s1 = sn[sp1 * 32 + pair];
                *(__half2*)&C[(size_t)row * Nout + col] =
                    __floats2half2_rn(a[0] * c0 - a[1] * s0, a[0] * s0 + a[1] * c0);
                *(__half2*)&C[(size_t)(row + 8) * Nout + col] =
                    __floats2half2_rn(a[2] * c1 - a[3] * s1, a[2] * s1 + a[3] * c1);
            } else {
                *(__half2*)&C[(size_t)row * Nout + col] = __floats2half2_rn(a[0], a[1]);
                *(__half2*)&C[(size_t)(row + 8) * Nout + col] = __floats2half2_rn(a[2], a[3]);
            }
        }
    }
}

// ---------------------------------------------------------------------------
// Output projection: O[4096,2048] @ Wo[2048,2048] -> out (fp32)
// ---------------------------------------------------------------------------
__global__ __launch_bounds__(256, 2) void gemm_out(
    const __half* __restrict__ A, const __half* __restrict__ B,
    float* __restrict__ C, int N, int K)
{
    __shared__ __half As[2][128][40];
    __shared__ __half Bs[2][32][136];

    const int brow = blockIdx.y * 128;
    const int bcol = blockIdx.x * 128;

    GemmCtx cx;
    gemm_mainloop(A, B, N, K, brow, bcol, As, Bs, cx);

#pragma unroll
    for (int mi = 0; mi < 4; mi++) {
#pragma unroll
        for (int ni = 0; ni < 4; ni++) {
            const int row = brow + cx.wm + mi * 16 + cx.g;
            const int col = bcol + cx.wn + ni * 8 + 2 * cx.tg;
            *(float2*)&C[(size_t)row * N + col] =
                make_float2(cx.acc[mi][ni][0], cx.acc[mi][ni][1]);
            *(float2*)&C[(size_t)(row + 8) * N + col] =
                make_float2(cx.acc[mi][ni][2], cx.acc[mi][ni][3]);
        }
    }
}

// ---------------------------------------------------------------------------
// fp16 tensor-core flash attention (causal, GQA 4:1) — unchanged from R8.
// ---------------------------------------------------------------------------
#define FS 72

__global__ __launch_bounds__(256) void flash_h(
    const __half* __restrict__ Q, const __half* __restrict__ K,
    const __half* __restrict__ V, __half* __restrict__ O)
{
    __shared__ __half fsm[2][128 * FS];
    __half* Qs = fsm[0];

    const int bh  = blockIdx.y;
    const int b   = bh >> 5;
    const int h   = bh & 31;
    const int kvh = h >> 2;
    const int qb  = gridDim.x - 1 - blockIdx.x;
    const int q0  = qb * 128;

    const int tid = threadIdx.x;
    const int wid = tid >> 5;
    const int lid = tid & 31;
    const int g   = lid >> 2;
    const int tg  = lid & 3;
    const int wq  = wid * 16;

    const int a_r = (lid & 15);
    const int a_c = 8 * (lid >> 4);
    const int nt_r = (lid & 7) + 8 * (lid >> 4);
    const int nt_c = 8 * ((lid >> 3) & 1);
    const int tr_r = (lid & 7) + 8 * ((lid >> 3) & 1);
    const int tr_c = 8 * (lid >> 4);

    {
        const int row = tid >> 1, c0 = (tid & 1) * 32;
        const __half* src = &Q[((size_t)(b * Sq + q0 + row)) * QDIM + h * HDq + c0];
        const __half2 hs = __floats2half2_rn(0.125f, 0.125f);
#pragma unroll
        for (int i = 0; i < 4; i++) {
            uint4 u = *(const uint4*)(src + 8 * i);
            __half2* hp = (__half2*)&u;
#pragma unroll
            for (int j = 0; j < 4; j++) hp[j] = __hmul2(hp[j], hs);
            *(uint4*)&Qs[row * FS + c0 + 8 * i] = u;
        }
    }
    __syncthreads();

    uint32_t qf[4][4];
#pragma unroll
    for (int kc = 0; kc < 4; kc++)
        LDSM4(qf[kc][0], qf[kc][1], qf[kc][2], qf[kc][3],
              s2u(&Qs[(wq + a_r) * FS + kc * 16 + a_c]));
    __syncthreads();

    float oacc[8][4];
#pragma unroll
    for (int nj = 0; nj < 8; nj++)
#pragma unroll
        for (int q = 0; q < 4; q++) oacc[nj][q] = 0.f;
    float m0 = -1e30f, m1 = -1e30f, l0 = 0.f, l1 = 0.f;

    const int ntiles = 2 * qb + 2;
    const int row0 = q0 + wq + g;
    const int row1 = row0 + 8;

    const int kvrow = tid >> 2, kvc = (tid & 3) * 16;
    const size_t kvbase = ((size_t)b * Sq + kvrow) * KVDIM + kvh * HDq + kvc;

    {
        __half* Ks = fsm[0];
        __half* Vs = fsm[0] + 64 * FS;
        const __half* kp = K + kvbase;
        const __half* vp = V + kvbase;
#pragma unroll
        for (int i = 0; i < 2; i++) {
            CP16(s2u(&Ks[kvrow * FS + kvc + 8 * i]), kp + 8 * i);
            CP16(s2u(&Vs[kvrow * FS + kvc + 8 * i]), vp + 8 * i);
        }
        CP_COMMIT();
    }

    for (int t = 0; t < ntiles; t++) {
        const int cur = t & 1;
        const bool has_next = (t + 1) < ntiles;
        if (has_next) {
            __half* Ks = fsm[cur ^ 1];
            __half* Vs = fsm[cur ^ 1] + 64 * FS;
            const size_t off = kvbase + (size_t)(t + 1) * 64 * KVDIM;
            const __half* kp = K + off;
            const __half* vp = V + off;
#pragma unroll
            for (int i = 0; i < 2; i++) {
                CP16(s2u(&Ks[kvrow * FS + kvc + 8 * i]), kp + 8 * i);
                CP16(s2u(&Vs[kvrow * FS + kvc + 8 * i]), vp + 8 * i);
            }
            CP_COMMIT();
            CP_WAIT1();
        } else {
            CP_WAIT0();
        }
        __syncthreads();

        const __half* Ks = fsm[cur];
        const __half* Vs = fsm[cur] + 64 * FS;
        const int tb = t * 64;

        float sacc[8][4];
#pragma unroll
        for (int ni = 0; ni < 8; ni++)
#pragma unroll
            for (int q = 0; q < 4; q++) sacc[ni][q] = 0.f;

#pragma unroll
        for (int kc = 0; kc < 4; kc++) {
#pragma unroll
            for (int ng = 0; ng < 4; ng++) {
                uint32_t kf[4];
                LDSM4(kf[0], kf[1], kf[2], kf[3],
                      s2u(&Ks[(ng * 16 + nt_r) * FS + kc * 16 + nt_c]));
                MMA_F16(sacc[2 * ng],     qf[kc][0], qf[kc][1], qf[kc][2], qf[kc][3], kf[0], kf[1]);
                MMA_F16(sacc[2 * ng + 1], qf[kc][0], qf[kc][1], qf[kc][2], qf[kc][3], kf[2], kf[3]);
            }
        }

        if (tb + 63 > q0 + wq) {
#pragma unroll
            for (int ni = 0; ni < 8; ni++) {
                int key = tb + 8 * ni + 2 * tg;
                if (key > row0)     sacc[ni][0] = -1e30f;
                if (key + 1 > row0) sacc[ni][1] = -1e30f;
                if (key > row1)     sacc[ni][2] = -1e30f;
                if (key + 1 > row1) sacc[ni][3] = -1e30f;
            }
        }

        float tmax0 = -1e30f, tmax1 = -1e30f;
#pragma unroll
        for (int ni = 0; ni < 8; ni++) {
            tmax0 = fmaxf(tmax0, fmaxf(sacc[ni][0], sacc[ni][1]));
            tmax1 = fmaxf(tmax1, fmaxf(sacc[ni][2], sacc[ni][3]));
        }
        tmax0 = fmaxf(tmax0, __shfl_xor_sync(0xffffffff, tmax0, 1));
        tmax0 = fmaxf(tmax0, __shfl_xor_sync(0xffffffff, tmax0, 2));
        tmax1 = fmaxf(tmax1, __shfl_xor_sync(0xffffffff, tmax1, 1));
        tmax1 = fmaxf(tmax1, __shfl_xor_sync(0xffffffff, tmax1, 2));

        float nm0 = fmaxf(m0, tmax0);
        float nm1 = fmaxf(m1, tmax1);
        float corr0 = __expf(m0 - nm0);
        float corr1 = __expf(m1 - nm1);

        float pv[8][4];
        float rs0 = 0.f, rs1 = 0.f;
#pragma unroll
        for (int ni = 0; ni < 8; ni++) {
            pv[ni][0] = __expf(sacc[ni][0] - nm0);
            pv[ni][1] = __expf(sacc[ni][1] - nm0);
            pv[ni][2] = __expf(sacc[ni][2] - nm1);
            pv[ni][3] = __expf(sacc[ni][3] - nm1);
            rs0 += pv[ni][0] + pv[ni][1];
            rs1 += pv[ni][2] + pv[ni][3];
        }
        rs0 += __shfl_xor_sync(0xffffffff, rs0, 1);
        rs0 += __shfl_xor_sync(0xffffffff, rs0, 2);
        rs1 += __shfl_xor_sync(0xffffffff, rs1, 1);
        rs1 += __shfl_xor_sync(0xffffffff, rs1, 2);

        l0 = l0 * corr0 + rs0;
        l1 = l1 * corr1 + rs1;
#pragma unroll
        for (int nj = 0; nj < 8; nj++) {
            oacc[nj][0] *= corr0;
            oacc[nj][1] *= corr0;
            oacc[nj][2] *= corr1;
            oacc[nj][3] *= corr1;
        }
        m0 = nm0;
        m1 = nm1;

#pragma unroll
        for (int kc = 0; kc < 4; kc++) {
            uint32_t a0 = f2h2u(pv[2 * kc][0], pv[2 * kc][1]);
            uint32_t a1 = f2h2u(pv[2 * kc][2], pv[2 * kc][3]);
            uint32_t a2 = f2h2u(pv[2 * kc + 1][0], pv[2 * kc + 1][1]);
            uint32_t a3 = f2h2u(pv[2 * kc + 1][2], pv[2 * kc + 1][3]);
#pragma unroll
            for (int ng = 0; ng < 4; ng++) {
                uint32_t vf[4];
                LDSM4T(vf[0], vf[1], vf[2], vf[3],
                       s2u(&Vs[(kc * 16 + tr_r) * FS + ng * 16 + tr_c]));
                MMA_F16(oacc[2 * ng],     a0, a1, a2, a3, vf[0], vf[1]);
                MMA_F16(oacc[2 * ng + 1], a0, a1, a2, a3, vf[2], vf[3]);
            }
        }
        __syncthreads();
    }

    float inv0 = 1.f / l0;
    float inv1 = 1.f / l1;
    const size_t tok0 = (size_t)b * Sq + row0;
#pragma unroll
    for (int nj = 0; nj < 8; nj++) {
        const int col = h * HDq + 8 * nj + 2 * tg;
        *(__half2*)&O[tok0 * QDIM + col] =
            __floats2half2_rn(oacc[nj][0] * inv0, oacc[nj][1] * inv0);
        *(__half2*)&O[(tok0 + 8) * QDIM + col] =
            __floats2half2_rn(oacc[nj][2] * inv1, oacc[nj][3] * inv1);
    }
}

// ---------------------------------------------------------------------------
// Launch
// ---------------------------------------------------------------------------
extern "C" void kernel_launch(void* const* d_in, const int* in_sizes, int n_in,
                              void* d_out, int out_size)
{
    const float* x   = (const float*)d_in[0];
    const float* cs  = (const float*)d_in[1];
    const float* sn  = (const float*)d_in[2];
    const float* Wq  = (const float*)d_in[3];
    const float* Wk  = (const float*)d_in[4];
    const float* Wv  = (const float*)d_in[5];
    const float* Wo  = (const float*)d_in[6];
    float* out = (float*)d_out;

    __half *Xh, *Wcat, *Woh, *Q, *K, *V, *O;
    cudaGetSymbolAddress((void**)&Xh, g_Xh);
    cudaGetSymbolAddress((void**)&Wcat, g_Wcat);
    cudaGetSymbolAddress((void**)&Woh, g_Woh);
    cudaGetSymbolAddress((void**)&Q, g_Q);
    cudaGetSymbolAddress((void**)&K, g_K);
    cudaGetSymbolAddress((void**)&V, g_V);
    cudaGetSymbolAddress((void**)&O, g_O);

    // fp32 -> fp16 staging (weights concatenated into [K, 3072])
    cvt_h<<<NTOK * DIMq / 8 / 256, 256>>>(x, Xh, NTOK * DIMq);
    cvt_cat<<<DIMq * QDIM / 8 / 256, 256>>>(Wq, Wcat, QDIM, 0, DIMq * QDIM);
    cvt_cat<<<DIMq * KVDIM / 8 / 256, 256>>>(Wk, Wcat, KVDIM, QDIM, DIMq * KVDIM);
    cvt_cat<<<DIMq * KVDIM / 8 / 256, 256>>>(Wv, Wcat, KVDIM, QDIM + KVDIM, DIMq * KVDIM);
    cvt_h<<<QDIM * DIMq / 8 / 256, 256>>>(Wo, Woh, QDIM * DIMq);

    // Fused QKV projection (+RoPE on Q,K)
    gemm_qkv<<<dim3(NCAT / 128, NTOK / 128), 256>>>(Xh, Wcat, Q, K, V, cs, sn);

    // fp16 flash attention
    flash_h<<<dim3(Sq / 128, Bq * NHq), 256>>>(Q, K, V, O);

    // Output projection (fp32 out)
    gemm_out<<<dim3(DIMq / 128, NTOK / 128), 256>>>(O, Woh, out, DIMq, QDIM);
}

// round 10
// speedup vs baseline: 7.7896x; 1.1201x over previous
#include <cuda_runtime.h>
#include <cuda_fp16.h>
#include <cstdint>

// Problem constants
#define Bq 2
#define Sq 2048
#define DIMq 2048
#define NHq 32
#define NKVq 8
#define HDq 64
#define NTOK (Bq * Sq)          // 4096
#define QDIM (NHq * HDq)        // 2048
#define KVDIM (NKVq * HDq)      // 512
#define NCAT (QDIM + 2 * KVDIM) // 3072

// ---------------------------------------------------------------------------
// Scratch (__device__ globals; no allocation allowed)
// ---------------------------------------------------------------------------
__device__ __align__(16) __half g_Xh[NTOK * DIMq];     // 16 MB fp16 x
__device__ __align__(16) __half g_Wcat[DIMq * NCAT];   // 12 MB [K, Nq|Nk|Nv]
__device__ __align__(16) __half g_Woh[QDIM * DIMq];    // 8 MB
__device__ __align__(16) __half g_Q[NTOK * QDIM];      // 16 MB (post-RoPE)
__device__ __align__(16) __half g_K[NTOK * KVDIM];     // 4 MB
__device__ __align__(16) __half g_V[NTOK * KVDIM];     // 4 MB
__device__ __align__(16) __half g_O[NTOK * QDIM];      // 16 MB

__device__ __forceinline__ uint32_t s2u(const void* p) {
    return (uint32_t)__cvta_generic_to_shared(p);
}
__device__ __forceinline__ uint32_t f2h2u(float x, float y) {
    __half2 h = __floats2half2_rn(x, y);
    return *(uint32_t*)&h;
}

#define LDSM4(r0, r1, r2, r3, addr)                                          \
    asm volatile("ldmatrix.sync.aligned.m8n8.x4.shared.b16 {%0,%1,%2,%3}, [%4];" \
                 : "=r"(r0), "=r"(r1), "=r"(r2), "=r"(r3) : "r"(addr))
#define LDSM4T(r0, r1, r2, r3, addr)                                         \
    asm volatile("ldmatrix.sync.aligned.m8n8.x4.trans.shared.b16 {%0,%1,%2,%3}, [%4];" \
                 : "=r"(r0), "=r"(r1), "=r"(r2), "=r"(r3) : "r"(addr))
#define MMA_F16(c, a0, a1, a2, a3, b0, b1)                                   \
    asm volatile(                                                            \
        "mma.sync.aligned.m16n8k16.row.col.f32.f16.f16.f32 "                 \
        "{%0,%1,%2,%3}, {%4,%5,%6,%7}, {%8,%9}, {%0,%1,%2,%3};"              \
        : "+f"((c)[0]), "+f"((c)[1]), "+f"((c)[2]), "+f"((c)[3])             \
        : "r"(a0), "r"(a1), "r"(a2), "r"(a3), "r"(b0), "r"(b1))
#define CP16(dst, src)                                                       \
    asm volatile("cp.async.ca.shared.global [%0], [%1], 16;"                 \
                 :: "r"(dst), "l"(src) : "memory")
#define CP_COMMIT() asm volatile("cp.async.commit_group;" ::: "memory")
#define CP_WAIT1()  asm volatile("cp.async.wait_group 1;" ::: "memory")

// ---------------------------------------------------------------------------
// One fused fp32->fp16 staging kernel. 2048 elems per block (256 thr x 8).
// Regions: x(4096 blk) | Wq(2048) | Wk(512) | Wv(512) | Wo(2048) = 9216.
// ---------------------------------------------------------------------------
__global__ void stage_all(
    const float* __restrict__ x, const float* __restrict__ Wq,
    const float* __restrict__ Wk, const float* __restrict__ Wv,
    const float* __restrict__ Wo,
    __half* __restrict__ Xh, __half* __restrict__ Wcat, __half* __restrict__ Woh)
{
    const int blk = blockIdx.x;
    const int t8  = threadIdx.x * 8;
    const float* src;
    __half* dst;
    if (blk < 4096) {
        int i = blk * 2048 + t8;
        src = x + i;
        dst = Xh + i;
    } else if (blk < 6144) {
        int i = (blk - 4096) * 2048 + t8;
        src = Wq + i;
        dst = Wcat + (size_t)(i / QDIM) * NCAT + (i % QDIM);
    } else if (blk < 6656) {
        int i = (blk - 6144) * 2048 + t8;
        src = Wk + i;
        dst = Wcat + (size_t)(i / KVDIM) * NCAT + QDIM + (i % KVDIM);
    } else if (blk < 7168) {
        int i = (blk - 6656) * 2048 + t8;
        src = Wv + i;
        dst = Wcat + (size_t)(i / KVDIM) * NCAT + QDIM + KVDIM + (i % KVDIM);
    } else {
        int i = (blk - 7168) * 2048 + t8;
        src = Wo + i;
        dst = Woh + i;
    }
    float4 a = *(const float4*)src;
    float4 b = *(const float4*)(src + 4);
    uint4 u;
    u.x = f2h2u(a.x, a.y);
    u.y = f2h2u(a.z, a.w);
    u.z = f2h2u(b.x, b.y);
    u.w = f2h2u(b.z, b.w);
    *(uint4*)dst = u;
}

// ---------------------------------------------------------------------------
// Shared GEMM mainloop: BK=32, CTA 128x128, 8 warps (2x4) of 64x32.
// 3-stage cp.async ring, ONE __syncthreads per chunk.
// Dynamic smem: As[3][128][40] + Bs[3][32][136] halfs = 56832 bytes.
// ---------------------------------------------------------------------------
#define AS_STAGE (128 * 40)
#define BS_STAGE (32 * 136)
#define GEMM_SMEM ((3 * AS_STAGE + 3 * BS_STAGE) * 2)  // 56832 B

struct GemmCtx {
    int wm, wn, g, tg;
    float acc[4][4][4];
};

__device__ __forceinline__ void gemm_mainloop(
    const __half* __restrict__ A, const __half* __restrict__ B,
    int N, int K, int brow, int bcol, __half* gsm, GemmCtx& cx)
{
    __half (*As)[128][40] = (__half(*)[128][40])gsm;
    __half (*Bs)[32][136] = (__half(*)[32][136])(gsm + 3 * AS_STAGE);

    const int tid = threadIdx.x;
    const int wid = tid >> 5;
    const int lid = tid & 31;
    cx.g  = lid >> 2;
    cx.tg = lid & 3;
    cx.wm = (wid & 1) * 64;
    cx.wn = (wid >> 1) * 32;

    const int ar = tid >> 1, ac = (tid & 1) * 16;
    const int brr = tid >> 3, bcc = (tid & 7) * 16;
    const __half* Ap = A + (size_t)(brow + ar) * K + ac;
    const __half* Bp = B + (size_t)brr * N + bcol + bcc;

    const int a_r = cx.wm + (lid & 15);
    const int a_c = 8 * (lid >> 4);
    const int b_k = (lid & 7) + 8 * ((lid >> 3) & 1);
    const int b_n = 8 * (lid >> 4);

#pragma unroll
    for (int mi = 0; mi < 4; mi++)
#pragma unroll
        for (int ni = 0; ni < 4; ni++)
#pragma unroll
            for (int q = 0; q < 4; q++) cx.acc[mi][ni][q] = 0.f;

    const int NC = K >> 5;

    // Prologue: chunks 0,1 -> stages 0,1 (two groups)
#pragma unroll
    for (int s = 0; s < 2; s++) {
        const __half* An = Ap + (s << 5);
        const __half* Bn = Bp + (size_t)(s << 5) * N;
        CP16(s2u(&As[s][ar][ac]), An);
        CP16(s2u(&As[s][ar][ac + 8]), An + 8);
        CP16(s2u(&Bs[s][brr][bcc]), Bn);
        CP16(s2u(&Bs[s][brr][bcc + 8]), Bn + 8);
        CP_COMMIT();
    }

    for (int kc = 0; kc < NC; kc++) {
        CP_WAIT1();          // stage kc%3 resident
        __syncthreads();     // all threads done with stage (kc-1)%3 reads

        const int cur = kc % 3;
#pragma unroll
        for (int ks = 0; ks < 2; ks++) {
            uint32_t af[4][4];
#pragma unroll
            for (int mi = 0; mi < 4; mi++)
                LDSM4(af[mi][0], af[mi][1], af[mi][2], af[mi][3],
                      s2u(&As[cur][a_r + mi * 16][ks * 16 + a_c]));
            uint32_t bf[4][2];
#pragma unroll
            for (int nq = 0; nq < 2; nq++)
                LDSM4T(bf[2 * nq][0], bf[2 * nq][1],
                       bf[2 * nq + 1][0], bf[2 * nq + 1][1],
                       s2u(&Bs[cur][ks * 16 + b_k][cx.wn + nq * 16 + b_n]));
#pragma unroll
            for (int mi = 0; mi < 4; mi++)
#pragma unroll
                for (int ni = 0; ni < 4; ni++)
                    MMA_F16(cx.acc[mi][ni], af[mi][0], af[mi][1], af[mi][2], af[mi][3],
                            bf[ni][0], bf[ni][1]);
        }

        const int nxt = kc + 2;
        if (nxt < NC) {
            const int sb = nxt % 3;
            const __half* An = Ap + (nxt << 5);
            const __half* Bn = Bp + (size_t)(nxt << 5) * N;
            CP16(s2u(&As[sb][ar][ac]), An);
            CP16(s2u(&As[sb][ar][ac + 8]), An + 8);
            CP16(s2u(&Bs[sb][brr][bcc]), Bn);
            CP16(s2u(&Bs[sb][brr][bcc + 8]), Bn + 8);
        }
        CP_COMMIT();         // always commit: keeps group counting uniform
    }
}

// ---------------------------------------------------------------------------
// Fused QKV projection: X @ Wcat -> Q (RoPE), K (RoPE), V, all fp16.
// ---------------------------------------------------------------------------
__global__ __launch_bounds__(256, 2) void gemm_qkv(
    const __half* __restrict__ X, const __half* __restrict__ Wc,
    __half* __restrict__ Q, __half* __restrict__ K, __half* __restrict__ V,
    const float* __restrict__ cs, const float* __restrict__ sn)
{
    extern __shared__ __half gsm[];
    const int brow = blockIdx.y * 128;
    const int bcol = blockIdx.x * 128;

    GemmCtx cx;
    gemm_mainloop(X, Wc, NCAT, DIMq, brow, bcol, gsm, cx);

    __half* C;
    int coff, Nout;
    bool rope;
    if (bcol < QDIM)              { C = Q; coff = 0;            Nout = QDIM;  rope = true;  }
    else if (bcol < QDIM + KVDIM) { C = K; coff = QDIM;         Nout = KVDIM; rope = true;  }
    else                          { C = V; coff = QDIM + KVDIM; Nout = KVDIM; rope = false; }

#pragma unroll
    for (int mi = 0; mi < 4; mi++) {
#pragma unroll
        for (int ni = 0; ni < 4; ni++) {
            const int row = brow + cx.wm + mi * 16 + cx.g;
            const int col = bcol - coff + cx.wn + ni * 8 + 2 * cx.tg;
            float* a = cx.acc[mi][ni];
            if (rope) {
                const int pair = (col & 63) >> 1;
                const int sp0 = row & (Sq - 1);
                const int sp1 = (row + 8) & (Sq - 1);
                float c0 = cs[sp0 * 32 + pair], s0 = sn[sp0 * 32 + pair];
                float c1 = cs[sp1 * 32 + pair], s1 = sn[sp1 * 32 + pair];
                *(__half2*)&C[(size_t)row * Nout + col] =
                    __floats2half2_rn(a[0] * c0 - a[1] * s0, a[0] * s0 + a[1] * c0);
                *(__half2*)&C[(size_t)(row + 8) * Nout + col] =
                    __floats2half2_rn(a[2] * c1 - a[3] * s1, a[2] * s1 + a[3] * c1);
            } else {
                *(__half2*)&C[(size_t)row * Nout + col] = __floats2half2_rn(a[0], a[1]);
                *(__half2*)&C[(size_t)(row + 8) * Nout + col] = __floats2half2_rn(a[2], a[3]);
            }
        }
    }
}

// ---------------------------------------------------------------------------
// Output projection: O @ Wo -> out (fp32)
// ---------------------------------------------------------------------------
__global__ __launch_bounds__(256, 2) void gemm_out(
    const __half* __restrict__ A, const __half* __restrict__ B,
    float* __restrict__ C, int N, int K)
{
    extern __shared__ __half gsm[];
    const int brow = blockIdx.y * 128;
    const int bcol = blockIdx.x * 128;

    GemmCtx cx;
    gemm_mainloop(A, B, N, K, brow, bcol, gsm, cx);

#pragma unroll
    for (int mi = 0; mi < 4; mi++) {
#pragma unroll
        for (int ni = 0; ni < 4; ni++) {
            const int row = brow + cx.wm + mi * 16 + cx.g;
            const int col = bcol + cx.wn + ni * 8 + 2 * cx.tg;
            *(float2*)&C[(size_t)row * N + col] =
                make_float2(cx.acc[mi][ni][0], cx.acc[mi][ni][1]);
            *(float2*)&C[(size_t)(row + 8) * N + col] =
                make_float2(cx.acc[mi][ni][2], cx.acc[mi][ni][3]);
        }
    }
}

// ---------------------------------------------------------------------------
// fp16 flash attention (causal, GQA 4:1): 3-stage KV ring, exp-in-place,
// 2 CTAs/SM. Dynamic smem: 3 stages x (K[64][72] + V[64][72]) = 55296 B.
// ---------------------------------------------------------------------------
#define FS 72
#define KV_STAGE (128 * FS)
#define FLASH_SMEM (3 * KV_STAGE * 2)  // 55296 B

__global__ __launch_bounds__(256, 2) void flash_h(
    const __half* __restrict__ Q, const __half* __restrict__ K,
    const __half* __restrict__ V, __half* __restrict__ O)
{
    extern __shared__ __half fsm[];

    const int bh  = blockIdx.y;
    const int b   = bh >> 5;
    const int h   = bh & 31;
    const int kvh = h >> 2;
    const int qb  = gridDim.x - 1 - blockIdx.x;   // heavy CTAs first
    const int q0  = qb * 128;

    const int tid = threadIdx.x;
    const int wid = tid >> 5;
    const int lid = tid & 31;
    const int g   = lid >> 2;
    const int tg  = lid & 3;
    const int wq  = wid * 16;

    const int a_r = (lid & 15);
    const int a_c = 8 * (lid >> 4);
    const int nt_r = (lid & 7) + 8 * (lid >> 4);
    const int nt_c = 8 * ((lid >> 3) & 1);
    const int tr_r = (lid & 7) + 8 * ((lid >> 3) & 1);
    const int tr_c = 8 * (lid >> 4);

    // ---- Q tile -> stage-0 buffer (staging), extract fragments ----
    {
        __half* Qs = fsm;
        const int row = tid >> 1, c0 = (tid & 1) * 32;
        const __half* src = &Q[((size_t)(b * Sq + q0 + row)) * QDIM + h * HDq + c0];
        const __half2 hs = __floats2half2_rn(0.125f, 0.125f);
#pragma unroll
        for (int i = 0; i < 4; i++) {
            uint4 u = *(const uint4*)(src + 8 * i);
            __half2* hp = (__half2*)&u;
#pragma unroll
            for (int j = 0; j < 4; j++) hp[j] = __hmul2(hp[j], hs);
            *(uint4*)&Qs[row * FS + c0 + 8 * i] = u;
        }
    }
    __syncthreads();

    uint32_t qf[4][4];
#pragma unroll
    for (int kc = 0; kc < 4; kc++)
        LDSM4(qf[kc][0], qf[kc][1], qf[kc][2], qf[kc][3],
              s2u(&fsm[(wq + a_r) * FS + kc * 16 + a_c]));
    __syncthreads();  // Q frags in regs; stage 0 reusable

    float oacc[8][4];
#pragma unroll
    for (int nj = 0; nj < 8; nj++)
#pragma unroll
        for (int q = 0; q < 4; q++) oacc[nj][q] = 0.f;
    float m0 = -1e30f, m1 = -1e30f, l0 = 0.f, l1 = 0.f;

    const int ntiles = 2 * qb + 2;
    const int row0 = q0 + wq + g;
    const int row1 = row0 + 8;

    const int kvrow = tid >> 2, kvc = (tid & 3) * 16;
    const size_t kvbase = ((size_t)b * Sq + kvrow) * KVDIM + kvh * HDq + kvc;

    // Prologue: tiles 0,1 -> stages 0,1
#pragma unroll
    for (int s = 0; s < 2; s++) {
        __half* Ks = fsm + s * KV_STAGE;
        __half* Vs = Ks + 64 * FS;
        const size_t off = kvbase + (size_t)s * 64 * KVDIM;
#pragma unroll
        for (int i = 0; i < 2; i++) {
            CP16(s2u(&Ks[kvrow * FS + kvc + 8 * i]), K + off + 8 * i);
            CP16(s2u(&Vs[kvrow * FS + kvc + 8 * i]), V + off + 8 * i);
        }
        CP_COMMIT();
    }

    for (int t = 0; t < ntiles; t++) {
        CP_WAIT1();
        __syncthreads();

        const __half* Ks = fsm + (t % 3) * KV_STAGE;
        const __half* Vs = Ks + 64 * FS;
        const int tb = t * 64;

        // ---- S = Q @ K^T ----
        float sacc[8][4];
#pragma unroll
        for (int ni = 0; ni < 8; ni++)
#pragma unroll
            for (int q = 0; q < 4; q++) sacc[ni][q] = 0.f;

#pragma unroll
        for (int kc = 0; kc < 4; kc++) {
#pragma unroll
            for (int ng = 0; ng < 4; ng++) {
                uint32_t kf[4];
                LDSM4(kf[0], kf[1], kf[2], kf[3],
                      s2u(&Ks[(ng * 16 + nt_r) * FS + kc * 16 + nt_c]));
                MMA_F16(sacc[2 * ng],     qf[kc][0], qf[kc][1], qf[kc][2], qf[kc][3], kf[0], kf[1]);
                MMA_F16(sacc[2 * ng + 1], qf[kc][0], qf[kc][1], qf[kc][2], qf[kc][3], kf[2], kf[3]);
            }
        }

        // ---- Causal mask ----
        if (tb + 63 > q0 + wq) {
#pragma unroll
            for (int ni = 0; ni < 8; ni++) {
                int key = tb + 8 * ni + 2 * tg;
                if (key > row0)     sacc[ni][0] = -1e30f;
                if (key + 1 > row0) sacc[ni][1] = -1e30f;
                if (key > row1)     sacc[ni][2] = -1e30f;
                if (key + 1 > row1) sacc[ni][3] = -1e30f;
            }
        }

        // ---- Online softmax (exp in place into sacc) ----
        float tmax0 = -1e30f, tmax1 = -1e30f;
#pragma unroll
        for (int ni = 0; ni < 8; ni++) {
            tmax0 = fmaxf(tmax0, fmaxf(sacc[ni][0], sacc[ni][1]));
            tmax1 = fmaxf(tmax1, fmaxf(sacc[ni][2], sacc[ni][3]));
        }
        tmax0 = fmaxf(tmax0, __shfl_xor_sync(0xffffffff, tmax0, 1));
        tmax0 = fmaxf(tmax0, __shfl_xor_sync(0xffffffff, tmax0, 2));
        tmax1 = fmaxf(tmax1, __shfl_xor_sync(0xffffffff, tmax1, 1));
        tmax1 = fmaxf(tmax1, __shfl_xor_sync(0xffffffff, tmax1, 2));

        float nm0 = fmaxf(m0, tmax0);
        float nm1 = fmaxf(m1, tmax1);
        float corr0 = __expf(m0 - nm0);
        float corr1 = __expf(m1 - nm1);

        float rs0 = 0.f, rs1 = 0.f;
#pragma unroll
        for (int ni = 0; ni < 8; ni++) {
            sacc[ni][0] = __expf(sacc[ni][0] - nm0);
            sacc[ni][1] = __expf(sacc[ni][1] - nm0);
            sacc[ni][2] = __expf(sacc[ni][2] - nm1);
            sacc[ni][3] = __expf(sacc[ni][3] - nm1);
            rs0 += sacc[ni][0] + sacc[ni][1];
            rs1 += sacc[ni][2] + sacc[ni][3];
        }
        rs0 += __shfl_xor_sync(0xffffffff, rs0, 1);
        rs0 += __shfl_xor_sync(0xffffffff, rs0, 2);
        rs1 += __shfl_xor_sync(0xffffffff, rs1, 1);
        rs1 += __shfl_xor_sync(0xffffffff, rs1, 2);

        l0 = l0 * corr0 + rs0;
        l1 = l1 * corr1 + rs1;
#pragma unroll
        for (int nj = 0; nj < 8; nj++) {
            oacc[nj][0] *= corr0;
            oacc[nj][1] *= corr0;
            oacc[nj][2] *= corr1;
            oacc[nj][3] *= corr1;
        }
        m0 = nm0;
        m1 = nm1;

        // ---- O += P @ V ----
#pragma unroll
        for (int kc = 0; kc < 4; kc++) {
            uint32_t a0 = f2h2u(sacc[2 * kc][0], sacc[2 * kc][1]);
            uint32_t a1 = f2h2u(sacc[2 * kc][2], sacc[2 * kc][3]);
            uint32_t a2 = f2h2u(sacc[2 * kc + 1][0], sacc[2 * kc + 1][1]);
            uint32_t a3 = f2h2u(sacc[2 * kc + 1][2], sacc[2 * kc + 1][3]);
#pragma unroll
            for (int ng = 0; ng < 4; ng++) {
                uint32_t vf[4];
                LDSM4T(vf[0], vf[1], vf[2], vf[3],
                       s2u(&Vs[(kc * 16 + tr_r) * FS + ng * 16 + tr_c]));
                MMA_F16(oacc[2 * ng],     a0, a1, a2, a3, vf[0], vf[1]);
                MMA_F16(oacc[2 * ng + 1], a0, a1, a2, a3, vf[2], vf[3]);
            }
        }

        // ---- Prefetch tile t+2 into stage (t+2)%3 ----
        const int nxt = t + 2;
        if (nxt < ntiles) {
            __half* Kn = fsm + (nxt % 3) * KV_STAGE;
            __half* Vn = Kn + 64 * FS;
            const size_t off = kvbase + (size_t)nxt * 64 * KVDIM;
#pragma unroll
            for (int i = 0; i < 2; i++) {
                CP16(s2u(&Kn[kvrow * FS + kvc + 8 * i]), K + off + 8 * i);
                CP16(s2u(&Vn[kvrow * FS + kvc + 8 * i]), V + off + 8 * i);
            }
        }
        CP_COMMIT();
    }

    // ---- Normalize and write (fp16) ----
    float inv0 = 1.f / l0;
    float inv1 = 1.f / l1;
    const size_t tok0 = (size_t)b * Sq + row0;
#pragma unroll
    for (int nj = 0; nj < 8; nj++) {
        const int col = h * HDq + 8 * nj + 2 * tg;
        *(__half2*)&O[tok0 * QDIM + col] =
            __floats2half2_rn(oacc[nj][0] * inv0, oacc[nj][1] * inv0);
        *(__half2*)&O[(tok0 + 8) * QDIM + col] =
            __floats2half2_rn(oacc[nj][2] * inv1, oacc[nj][3] * inv1);
    }
}

// ---------------------------------------------------------------------------
// Launch
// ---------------------------------------------------------------------------
extern "C" void kernel_launch(void* const* d_in, const int* in_sizes, int n_in,
                              void* d_out, int out_size)
{
    const float* x   = (const float*)d_in[0];
    const float* cs  = (const float*)d_in[1];
    const float* sn  = (const float*)d_in[2];
    const float* Wq  = (const float*)d_in[3];
    const float* Wk  = (const float*)d_in[4];
    const float* Wv  = (const float*)d_in[5];
    const float* Wo  = (const float*)d_in[6];
    float* out = (float*)d_out;

    __half *Xh, *Wcat, *Woh, *Q, *K, *V, *O;
    cudaGetSymbolAddress((void**)&Xh, g_Xh);
    cudaGetSymbolAddress((void**)&Wcat, g_Wcat);
    cudaGetSymbolAddress((void**)&Woh, g_Woh);
    cudaGetSymbolAddress((void**)&Q, g_Q);
    cudaGetSymbolAddress((void**)&K, g_K);
    cudaGetSymbolAddress((void**)&V, g_V);
    cudaGetSymbolAddress((void**)&O, g_O);

    cudaFuncSetAttribute(gemm_qkv, cudaFuncAttributeMaxDynamicSharedMemorySize, GEMM_SMEM);
    cudaFuncSetAttribute(gemm_out, cudaFuncAttributeMaxDynamicSharedMemorySize, GEMM_SMEM);
    cudaFuncSetAttribute(flash_h, cudaFuncAttributeMaxDynamicSharedMemorySize, FLASH_SMEM);

    // One fused staging kernel
    stage_all<<<9216, 256>>>(x, Wq, Wk, Wv, Wo, Xh, Wcat, Woh);

    // Fused QKV projection (+RoPE on Q,K)
    gemm_qkv<<<dim3(NCAT / 128, NTOK / 128), 256, GEMM_SMEM>>>(Xh, Wcat, Q, K, V, cs, sn);

    // fp16 flash attention
    flash_h<<<dim3(Sq / 128, Bq * NHq), 256, FLASH_SMEM>>>(Q, K, V, O);

    // Output projection (fp32 out)
    gemm_out<<<dim3(DIMq / 128, NTOK / 128), 256, GEMM_SMEM>>>(O, Woh, out, DIMq, QDIM);
}